// round 9
// baseline (speedup 1.0000x reference)
#include <cuda_runtime.h>
#include <math.h>
#include <stdint.h>

// ---------------- problem constants ----------------
#define B_ 2
#define T_ 1024
#define C_ 1024
#define H_ 16
#define HD_ 64
#define L_ 12
#define V_ 50257
#define VPAD_ 50260          // V padded to multiple of 4 for vectorized B loads
#define MTOT (B_ * T_)      // 2048 token rows
#define FF_ (4 * C_)        // 4096

// ---------------- static device scratch ----------------
__device__ float g_x[MTOT * C_];
__device__ float g_h[MTOT * C_];
__device__ float g_q[MTOT * C_];
__device__ float g_k[MTOT * C_];
__device__ float g_v[MTOT * C_];
__device__ float g_y[MTOT * C_];
__device__ float g_mlp[MTOT * FF_];
__device__ float g_nll[MTOT];
__device__ float g_headw_pad[(size_t)C_ * VPAD_];    // 206 MB padded head weights
__device__ float g_logits[(size_t)MTOT * V_];        // fallback if d_out can't hold logits

// ---------------- helpers ----------------
__device__ __forceinline__ float gelu_exact(float v) {
    return 0.5f * v * (1.0f + erff(v * 0.7071067811865476f));
}

__device__ __forceinline__ uint32_t f2tf32(float x) {
    uint32_t r;
    asm("cvt.rna.tf32.f32 %0, %1;" : "=r"(r) : "f"(x));
    return r;
}

__device__ __forceinline__ uint32_t smem_u32(const void* p) {
    return (uint32_t)__cvta_generic_to_shared(p);
}

#define MMA_TF32(c, a0, a1, a2, a3, b0, b1)                                  \
    asm volatile(                                                            \
        "mma.sync.aligned.m16n8k8.row.col.f32.tf32.tf32.f32 "                \
        "{%0,%1,%2,%3}, {%4,%5,%6,%7}, {%8,%9}, {%0,%1,%2,%3};\n"            \
        : "+f"((c)[0]), "+f"((c)[1]), "+f"((c)[2]), "+f"((c)[3])             \
        : "r"(a0), "r"(a1), "r"(a2), "r"(a3), "r"(b0), "r"(b1))

#define CP_ASYNC16(dst, src)                                                 \
    asm volatile("cp.async.cg.shared.global [%0], [%1], 16;"                 \
                 :: "r"(dst), "l"(src))
#define CP_COMMIT() asm volatile("cp.async.commit_group;")
#define CP_WAIT(n)  asm volatile("cp.async.wait_group %0;" :: "n"(n) : "memory")

// ---------------- head weight padding copy: [C,V] -> [C,VPAD] ----------------
__global__ void pad_headw_kernel(const float* __restrict__ src,
                                 float* __restrict__ dst) {
    int row = blockIdx.x;                       // 0..C_-1
    const float* s = src + (size_t)row * V_;
    float* d = dst + (size_t)row * VPAD_;
    for (int c = threadIdx.x; c < V_; c += 256) d[c] = s[c];
    if (threadIdx.x < VPAD_ - V_) d[V_ + threadIdx.x] = 0.f;
}

// ---------------- embedding ----------------
__global__ void embed_kernel(const int* __restrict__ idx,
                             const float* __restrict__ tok,
                             const float* __restrict__ pos,
                             float* __restrict__ x) {
    int row = blockIdx.x;
    int t = row % T_;
    int id = idx[row];
    const float* tr = tok + (size_t)id * C_;
    const float* pr = pos + (size_t)t * C_;
    float* xr = x + (size_t)row * C_;
#pragma unroll
    for (int j = 0; j < 4; j++) {
        int c = threadIdx.x + j * 256;
        xr[c] = tr[c] + pr[c];
    }
}

// ---------------- layernorm ----------------
__global__ void layernorm_kernel(const float* __restrict__ x,
                                 const float* __restrict__ w,
                                 const float* __restrict__ b,
                                 float* __restrict__ out) {
    int row = blockIdx.x;
    int tid = threadIdx.x;
    const float* xr = x + (size_t)row * C_;
    float v[4];
    float s = 0.f;
#pragma unroll
    for (int j = 0; j < 4; j++) { v[j] = xr[tid + j * 256]; s += v[j]; }
    __shared__ float red[256];
    red[tid] = s; __syncthreads();
    for (int off = 128; off > 0; off >>= 1) {
        if (tid < off) red[tid] += red[tid + off];
        __syncthreads();
    }
    float mu = red[0] * (1.0f / C_);
    __syncthreads();
    float s2 = 0.f;
#pragma unroll
    for (int j = 0; j < 4; j++) { float d = v[j] - mu; s2 += d * d; }
    red[tid] = s2; __syncthreads();
    for (int off = 128; off > 0; off >>= 1) {
        if (tid < off) red[tid] += red[tid + off];
        __syncthreads();
    }
    float var = red[0] * (1.0f / C_);
    float rstd = rsqrtf(var + 1e-5f);
    float* orow = out + (size_t)row * C_;
#pragma unroll
    for (int j = 0; j < 4; j++) {
        int c = tid + j * 256;
        orow[c] = (v[j] - mu) * rstd * w[c] + b[c];
    }
}

// ---------------- TF32 tensor-core GEMM, cp.async 4-stage pipeline ----------------
#define AS_STRIDE 20
#define BS_STRIDE 136
#define GSTAGES 4
#define AS_ELEMS (128 * AS_STRIDE)
#define BS_ELEMS (16 * BS_STRIDE)
#define GEMM_SMEM ((AS_ELEMS + BS_ELEMS) * GSTAGES * 4)

template <int ACT, bool HAS_BIAS, bool HAS_RES>
__device__ __forceinline__ void gemm_body(const float* __restrict__ A, int lda,
                                          const float* __restrict__ Bm, int ldb,
                                          const float* __restrict__ bias,
                                          const float* __restrict__ resid, int ldr,
                                          float* __restrict__ Cm, int ldc,
                                          int M, int N, int K,
                                          int rowBase, int colBase) {
    extern __shared__ float dsm[];
    float* As = dsm;                           // [GSTAGES][AS_ELEMS]
    float* Bs = dsm + GSTAGES * AS_ELEMS;      // [GSTAGES][BS_ELEMS]

    const int tid = threadIdx.x;
    const int lane = tid & 31, warp = tid >> 5;
    const int g = lane >> 2, tg = lane & 3;
    const int wm = warp >> 1, wn = warp & 1;   // 2x2 warp grid

    float c[4][8][4];
#pragma unroll
    for (int i = 0; i < 4; i++)
#pragma unroll
        for (int j = 0; j < 8; j++)
#pragma unroll
            for (int r = 0; r < 4; r++) c[i][j][r] = 0.f;

    const bool vecB = ((ldb & 3) == 0) && (colBase + 128 <= N);

    auto loadA = [&](int s, int kt) {
        float* Ad = As + s * AS_ELEMS;
#pragma unroll
        for (int i = 0; i < 4; i++) {
            int lin = tid + i * 128;
            int r = lin >> 2, c4 = lin & 3;
            uint32_t dst = smem_u32(&Ad[r * AS_STRIDE + c4 * 4]);
            const float* src = A + (size_t)(rowBase + r) * lda + kt + c4 * 4;
            CP_ASYNC16(dst, src);
        }
    };
    auto loadB = [&](int s, int kt) {
        float* Bd = Bs + s * BS_ELEMS;
        if (vecB) {
#pragma unroll
            for (int i = 0; i < 4; i++) {
                int lin = tid + i * 128;
                int r = lin >> 5, c4 = lin & 31;
                uint32_t dst = smem_u32(&Bd[r * BS_STRIDE + c4 * 4]);
                const float* src = Bm + (size_t)(kt + r) * ldb + colBase + c4 * 4;
                CP_ASYNC16(dst, src);
            }
        } else {
#pragma unroll
            for (int i = 0; i < 16; i++) {
                int lin = tid + i * 128;
                int r = lin >> 7, cc = lin & 127;
                int gc = colBase + cc;
                uint32_t dst = smem_u32(&Bd[r * BS_STRIDE + cc]);
                int gcs = gc < N ? gc : (N - 1);
                const float* src = Bm + (size_t)(kt + r) * ldb + gcs;
                uint32_t ssz = (gc < N) ? 4u : 0u;
                asm volatile("cp.async.ca.shared.global [%0], [%1], 4, %2;"
                             :: "r"(dst), "l"(src), "r"(ssz));
            }
        }
    };

    const int nkt = K >> 4;                    // >= 64 for all our GEMMs
#pragma unroll
    for (int s = 0; s < GSTAGES - 1; s++) {    // prologue: 3 tiles in flight
        loadA(s, s * 16);
        loadB(s, s * 16);
        CP_COMMIT();
    }

    for (int t = 0; t < nkt; t++) {
        CP_WAIT(GSTAGES - 2);
        __syncthreads();
        int ld = t + GSTAGES - 1;
        if (ld < nkt) {
            loadA(ld & 3, ld * 16);
            loadB(ld & 3, ld * 16);
        }
        CP_COMMIT();

        const int s = t & 3;
        const float* Ap = As + s * AS_ELEMS;
        const float* Bp = Bs + s * BS_ELEMS;
#pragma unroll
        for (int k8 = 0; k8 < 16; k8 += 8) {
            uint32_t af[4][4], bf[8][2];
#pragma unroll
            for (int mt = 0; mt < 4; mt++) {
                int mrow = wm * 64 + mt * 16 + g;
                af[mt][0] = f2tf32(Ap[mrow * AS_STRIDE + k8 + tg]);
                af[mt][1] = f2tf32(Ap[(mrow + 8) * AS_STRIDE + k8 + tg]);
                af[mt][2] = f2tf32(Ap[mrow * AS_STRIDE + k8 + tg + 4]);
                af[mt][3] = f2tf32(Ap[(mrow + 8) * AS_STRIDE + k8 + tg + 4]);
            }
#pragma unroll
            for (int nt = 0; nt < 8; nt++) {
                int ncol = wn * 64 + nt * 8 + g;
                bf[nt][0] = f2tf32(Bp[(k8 + tg) * BS_STRIDE + ncol]);
                bf[nt][1] = f2tf32(Bp[(k8 + tg + 4) * BS_STRIDE + ncol]);
            }
#pragma unroll
            for (int mt = 0; mt < 4; mt++)
#pragma unroll
                for (int nt = 0; nt < 8; nt++)
                    MMA_TF32(c[mt][nt], af[mt][0], af[mt][1], af[mt][2], af[mt][3],
                             bf[nt][0], bf[nt][1]);
        }
    }

    // ---- epilogue ----
    const bool vecC = ((ldc & 1) == 0);
#pragma unroll
    for (int mt = 0; mt < 4; mt++) {
#pragma unroll
        for (int ri = 0; ri < 2; ri++) {
            int gr = rowBase + wm * 64 + mt * 16 + g + ri * 8;
#pragma unroll
            for (int nt = 0; nt < 8; nt++) {
                int gc = colBase + wn * 64 + nt * 8 + 2 * tg;
                if (gc >= N) continue;
                bool in1 = (gc + 1) < N;
                float v0 = c[mt][nt][ri * 2 + 0];
                float v1 = c[mt][nt][ri * 2 + 1];
                if (HAS_BIAS) { v0 += bias[gc]; if (in1) v1 += bias[gc + 1]; }
                if (ACT == 1) { v0 = gelu_exact(v0); if (in1) v1 = gelu_exact(v1); }
                if (HAS_RES) {
                    v0 += resid[(size_t)gr * ldr + gc];
                    if (in1) v1 += resid[(size_t)gr * ldr + gc + 1];
                }
                float* cp = Cm + (size_t)gr * ldc + gc;
                if (vecC && in1) {
                    *reinterpret_cast<float2*>(cp) = make_float2(v0, v1);
                } else {
                    cp[0] = v0;
                    if (in1) cp[1] = v1;
                }
            }
        }
    }
}

template <int ACT, bool HAS_BIAS, bool HAS_RES, bool SWAP>
__global__ void __launch_bounds__(128, 2)
gemm_tf32_kernel(const float* __restrict__ A, int lda,
                 const float* __restrict__ Bm, int ldb,
                 const float* __restrict__ bias,
                 const float* __restrict__ resid, int ldr,
                 float* __restrict__ Cm, int ldc,
                 int M, int N, int K) {
    int rowBase = (SWAP ? blockIdx.x : blockIdx.y) * 128;
    int colBase = (SWAP ? blockIdx.y : blockIdx.x) * 128;
    gemm_body<ACT, HAS_BIAS, HAS_RES>(A, lda, Bm, ldb, bias, resid, ldr,
                                      Cm, ldc, M, N, K, rowBase, colBase);
}

// fused QKV: blockIdx.z selects which projection
__global__ void __launch_bounds__(128, 2)
gemm_qkv_tf32_kernel(const float* __restrict__ h,
                     const float* __restrict__ Wq, const float* __restrict__ Wk,
                     const float* __restrict__ Wv,
                     const float* __restrict__ bq, const float* __restrict__ bk,
                     const float* __restrict__ bv,
                     float* __restrict__ qo, float* __restrict__ ko,
                     float* __restrict__ vo) {
    const float* Bm; const float* bias; float* Cm;
    if (blockIdx.z == 0)      { Bm = Wq; bias = bq; Cm = qo; }
    else if (blockIdx.z == 1) { Bm = Wk; bias = bk; Cm = ko; }
    else                      { Bm = Wv; bias = bv; Cm = vo; }
    gemm_body<0, true, false>(h, C_, Bm, C_, bias, nullptr, 0, Cm, C_, MTOT, C_, C_,
                              blockIdx.y * 128, blockIdx.x * 128);
}

// ---------------- fused flash attention (S and PV both on TF32 MMA) ----------------
#define QP 68
#define KP 68
#define VP 72
#define PP 68
#define FLASH_SMEM ((64 * QP + 2 * 64 * KP + 2 * 64 * VP + 64 * PP) * 4)

__global__ void __launch_bounds__(128, 2)
flash_attn_kernel(const float* __restrict__ q, const float* __restrict__ k,
                  const float* __restrict__ v, float* __restrict__ y) {
    extern __shared__ float sm[];
    float* Qs = sm;                       // [m][d]
    float* Ks = Qs + 64 * QP;             // 2 x [n][d]
    float* Vs = Ks + 2 * 64 * KP;         // 2 x [n][d]
    float* Ps = Vs + 2 * 64 * VP;         // [m][n]

    const int tid = threadIdx.x;
    const int lane = tid & 31, warp = tid >> 5;
    const int g = lane >> 2, tg = lane & 3;
    const int z = blockIdx.y;
    const int b = z >> 4, h = z & 15;
    const int qt = (T_ / 64 - 1) - blockIdx.x;   // heavy CTAs first
    const int rowBase = qt * 64;

    const float* qb = q + (size_t)b * T_ * C_ + h * HD_;
    const float* kb = k + (size_t)b * T_ * C_ + h * HD_;
    const float* vb = v + (size_t)b * T_ * C_ + h * HD_;
    float* yb = y + (size_t)b * T_ * C_ + h * HD_;

    auto loadKV = [&](int s, int kt) {
        const float* kbt = kb + (size_t)kt * 64 * C_;
        const float* vbt = vb + (size_t)kt * 64 * C_;
        float* Kd = Ks + s * 64 * KP;
        float* Vd = Vs + s * 64 * VP;
#pragma unroll
        for (int i = 0; i < 8; i++) {
            int lin = tid + i * 128;
            int n = lin >> 4, d4 = lin & 15;
            CP_ASYNC16(smem_u32(&Kd[n * KP + d4 * 4]), kbt + (size_t)n * C_ + d4 * 4);
        }
#pragma unroll
        for (int i = 0; i < 8; i++) {
            int lin = tid + i * 128;
            int n = lin >> 4, d4 = lin & 15;
            CP_ASYNC16(smem_u32(&Vd[n * VP + d4 * 4]), vbt + (size_t)n * C_ + d4 * 4);
        }
    };

    // Q tile (once) + first KV stage in one group
#pragma unroll
    for (int i = 0; i < 8; i++) {
        int lin = tid + i * 128;
        int mm = lin >> 4, d4 = lin & 15;
        CP_ASYNC16(smem_u32(&Qs[mm * QP + d4 * 4]), qb + (size_t)(rowBase + mm) * C_ + d4 * 4);
    }
    loadKV(0, 0);
    CP_COMMIT();

    const int r0 = warp * 16 + g, r1 = r0 + 8;   // rows owned (S and O share layout)
    float m0 = -INFINITY, m1 = -INFINITY, l0 = 0.f, l1 = 0.f;
    float of[8][4];
#pragma unroll
    for (int nt = 0; nt < 8; nt++)
#pragma unroll
        for (int r = 0; r < 4; r++) of[nt][r] = 0.f;

    for (int kt = 0; kt <= qt; kt++) {
        const int s = kt & 1;
        CP_WAIT(0);
        __syncthreads();
        if (kt < qt) loadKV(s ^ 1, kt + 1);
        CP_COMMIT();

        // ---- S = Q.K^T (TF32 MMA), K natural [n][d] read K-major ----
        const float* Kp = Ks + s * 64 * KP;
        float sf[8][4];
#pragma unroll
        for (int nt = 0; nt < 8; nt++)
#pragma unroll
            for (int r = 0; r < 4; r++) sf[nt][r] = 0.f;
#pragma unroll
        for (int k8 = 0; k8 < 64; k8 += 8) {
            uint32_t a0 = f2tf32(Qs[r0 * QP + k8 + tg]);
            uint32_t a1 = f2tf32(Qs[r1 * QP + k8 + tg]);
            uint32_t a2 = f2tf32(Qs[r0 * QP + k8 + tg + 4]);
            uint32_t a3 = f2tf32(Qs[r1 * QP + k8 + tg + 4]);
#pragma unroll
            for (int nt = 0; nt < 8; nt++) {
                int ncol = nt * 8 + g;
                uint32_t b0 = f2tf32(Kp[ncol * KP + k8 + tg]);
                uint32_t b1 = f2tf32(Kp[ncol * KP + k8 + tg + 4]);
                MMA_TF32(sf[nt], a0, a1, a2, a3, b0, b1);
            }
        }
#pragma unroll
        for (int nt = 0; nt < 8; nt++)
#pragma unroll
            for (int r = 0; r < 4; r++) sf[nt][r] *= 0.125f;   // 1/sqrt(HD)

        // ---- causal mask (diag tile only) ----
        if (kt == qt) {
            int gr0 = rowBase + r0, gr1 = rowBase + r1;
            int cb = kt * 64;
#pragma unroll
            for (int nt = 0; nt < 8; nt++) {
                int c0 = cb + nt * 8 + 2 * tg, c1 = c0 + 1;
                if (c0 > gr0) sf[nt][0] = -1e30f;
                if (c1 > gr0) sf[nt][1] = -1e30f;
                if (c0 > gr1) sf[nt][2] = -1e30f;
                if (c1 > gr1) sf[nt][3] = -1e30f;
            }
        }

        // ---- online softmax (registers only; quad-shuffle reductions) ----
        float mx0 = -INFINITY, mx1 = -INFINITY;
#pragma unroll
        for (int nt = 0; nt < 8; nt++) {
            mx0 = fmaxf(mx0, fmaxf(sf[nt][0], sf[nt][1]));
            mx1 = fmaxf(mx1, fmaxf(sf[nt][2], sf[nt][3]));
        }
        mx0 = fmaxf(mx0, __shfl_xor_sync(0xFFFFFFFF, mx0, 1));
        mx0 = fmaxf(mx0, __shfl_xor_sync(0xFFFFFFFF, mx0, 2));
        mx1 = fmaxf(mx1, __shfl_xor_sync(0xFFFFFFFF, mx1, 1));
        mx1 = fmaxf(mx1, __shfl_xor_sync(0xFFFFFFFF, mx1, 2));

        float mn0 = fmaxf(m0, mx0), mn1 = fmaxf(m1, mx1);
        float a0s = __expf(m0 - mn0), a1s = __expf(m1 - mn1);

        float rs0 = 0.f, rs1 = 0.f;
#pragma unroll
        for (int nt = 0; nt < 8; nt++) {
            sf[nt][0] = __expf(sf[nt][0] - mn0);
            sf[nt][1] = __expf(sf[nt][1] - mn0);
            sf[nt][2] = __expf(sf[nt][2] - mn1);
            sf[nt][3] = __expf(sf[nt][3] - mn1);
            rs0 += sf[nt][0] + sf[nt][1];
            rs1 += sf[nt][2] + sf[nt][3];
        }
        rs0 += __shfl_xor_sync(0xFFFFFFFF, rs0, 1);
        rs0 += __shfl_xor_sync(0xFFFFFFFF, rs0, 2);
        rs1 += __shfl_xor_sync(0xFFFFFFFF, rs1, 1);
        rs1 += __shfl_xor_sync(0xFFFFFFFF, rs1, 2);

        m0 = mn0; m1 = mn1;
        l0 = l0 * a0s + rs0;
        l1 = l1 * a1s + rs1;

        // ---- P to smem (only this warp's rows; warp-local reuse) ----
#pragma unroll
        for (int nt = 0; nt < 8; nt++) {
            int cc = nt * 8 + 2 * tg;
            *reinterpret_cast<float2*>(&Ps[r0 * PP + cc]) = make_float2(sf[nt][0], sf[nt][1]);
            *reinterpret_cast<float2*>(&Ps[r1 * PP + cc]) = make_float2(sf[nt][2], sf[nt][3]);
        }
        __syncwarp();

        // ---- O = O*alpha + P.V (TF32 MMA), V natural [n][d] ----
#pragma unroll
        for (int nt = 0; nt < 8; nt++) {
            of[nt][0] *= a0s; of[nt][1] *= a0s;
            of[nt][2] *= a1s; of[nt][3] *= a1s;
        }
        const float* Vp = Vs + s * 64 * VP;
#pragma unroll
        for (int k8 = 0; k8 < 64; k8 += 8) {
            uint32_t a0 = f2tf32(Ps[r0 * PP + k8 + tg]);
            uint32_t a1 = f2tf32(Ps[r1 * PP + k8 + tg]);
            uint32_t a2 = f2tf32(Ps[r0 * PP + k8 + tg + 4]);
            uint32_t a3 = f2tf32(Ps[r1 * PP + k8 + tg + 4]);
#pragma unroll
            for (int nt = 0; nt < 8; nt++) {
                int ncol = nt * 8 + g;
                uint32_t b0 = f2tf32(Vp[(k8 + tg) * VP + ncol]);
                uint32_t b1 = f2tf32(Vp[(k8 + tg + 4) * VP + ncol]);
                MMA_TF32(of[nt], a0, a1, a2, a3, b0, b1);
            }
        }
    }

    // ---- epilogue: y = O / l (fragment layout direct to gmem) ----
    float inv0 = 1.0f / l0, inv1 = 1.0f / l1;
    float* yr0 = yb + (size_t)(rowBase + r0) * C_;
    float* yr1 = yb + (size_t)(rowBase + r1) * C_;
#pragma unroll
    for (int nt = 0; nt < 8; nt++) {
        int cc = nt * 8 + 2 * tg;
        *reinterpret_cast<float2*>(yr0 + cc) = make_float2(of[nt][0] * inv0, of[nt][1] * inv0);
        *reinterpret_cast<float2*>(yr1 + cc) = make_float2(of[nt][2] * inv1, of[nt][3] * inv1);
    }
}

// ---------------- per-row NLL over V (single-pass online) ----------------
__global__ void nll_kernel(const float* __restrict__ logits,
                           const int* __restrict__ targets,
                           float* __restrict__ nll) {
    int row = blockIdx.x;
    const float* p = logits + (size_t)row * V_;
    int tid = threadIdx.x;
    float m = -INFINITY, s = 0.f;
    for (int c = tid; c < V_; c += 256) {
        float v = p[c];
        if (v <= m) {
            s += expf(v - m);
        } else {
            s = s * expf(m - v) + 1.0f;
            m = v;
        }
    }
    __shared__ float rm[256], rs[256];
    rm[tid] = m; rs[tid] = s; __syncthreads();
    for (int off = 128; off > 0; off >>= 1) {
        if (tid < off) {
            float m1 = rm[tid], s1 = rs[tid];
            float m2 = rm[tid + off], s2 = rs[tid + off];
            float M = fmaxf(m1, m2);
            rm[tid] = M;
            rs[tid] = s1 * expf(m1 - M) + s2 * expf(m2 - M);
        }
        __syncthreads();
    }
    if (tid == 0) {
        float lt = p[targets[row]];
        nll[row] = -(lt - rm[0] - logf(rs[0]));
    }
}

__global__ void loss_kernel(const float* __restrict__ nll, float* __restrict__ out) {
    __shared__ float red[256];
    int tid = threadIdx.x;
    float s = 0.f;
    for (int c = tid; c < MTOT; c += 256) s += nll[c];
    red[tid] = s; __syncthreads();
    for (int off = 128; off > 0; off >>= 1) {
        if (tid < off) red[tid] += red[tid + off];
        __syncthreads();
    }
    if (tid == 0) out[0] = red[0] * (1.0f / MTOT);
}

// ---------------- host launcher ----------------
extern "C" void kernel_launch(void* const* d_in, const int* in_sizes, int n_in,
                              void* d_out, int out_size) {
    const int*   idx     = (const int*)d_in[0];
    const int*   targets = (const int*)d_in[1];
    const float* tok     = (const float*)d_in[2];
    const float* pos     = (const float*)d_in[3];
    const float* ln1w    = (const float*)d_in[4];
    const float* ln1b    = (const float*)d_in[5];
    const float* ln2w    = (const float*)d_in[6];
    const float* ln2b    = (const float*)d_in[7];
    const float* Wq      = (const float*)d_in[8];
    const float* bq      = (const float*)d_in[9];
    const float* Wk      = (const float*)d_in[10];
    const float* bk      = (const float*)d_in[11];
    const float* Wv      = (const float*)d_in[12];
    const float* bv      = (const float*)d_in[13];
    const float* Wo      = (const float*)d_in[14];
    const float* bo      = (const float*)d_in[15];
    const float* W1      = (const float*)d_in[16];
    const float* b1      = (const float*)d_in[17];
    const float* W2      = (const float*)d_in[18];
    const float* b2      = (const float*)d_in[19];
    const float* lnfw    = (const float*)d_in[20];
    const float* lnfb    = (const float*)d_in[21];
    const float* headw   = (const float*)d_in[22];
    float* out = (float*)d_out;

    float *x, *h, *q, *k, *v, *y, *mlp, *nllbuf, *lgs, *hwp;
    cudaGetSymbolAddress((void**)&x, g_x);
    cudaGetSymbolAddress((void**)&h, g_h);
    cudaGetSymbolAddress((void**)&q, g_q);
    cudaGetSymbolAddress((void**)&k, g_k);
    cudaGetSymbolAddress((void**)&v, g_v);
    cudaGetSymbolAddress((void**)&y, g_y);
    cudaGetSymbolAddress((void**)&mlp, g_mlp);
    cudaGetSymbolAddress((void**)&nllbuf, g_nll);
    cudaGetSymbolAddress((void**)&lgs, g_logits);
    cudaGetSymbolAddress((void**)&hwp, g_headw_pad);

    cudaFuncSetAttribute(flash_attn_kernel,
                         cudaFuncAttributeMaxDynamicSharedMemorySize, FLASH_SMEM);
    cudaFuncSetAttribute(gemm_qkv_tf32_kernel,
                         cudaFuncAttributeMaxDynamicSharedMemorySize, GEMM_SMEM);
    cudaFuncSetAttribute(gemm_tf32_kernel<0, true, true, false>,
                         cudaFuncAttributeMaxDynamicSharedMemorySize, GEMM_SMEM);
    cudaFuncSetAttribute(gemm_tf32_kernel<1, true, false, false>,
                         cudaFuncAttributeMaxDynamicSharedMemorySize, GEMM_SMEM);
    cudaFuncSetAttribute(gemm_tf32_kernel<0, false, false, true>,
                         cudaFuncAttributeMaxDynamicSharedMemorySize, GEMM_SMEM);

    const size_t BTV = (size_t)MTOT * V_;
    float* logits = ((size_t)out_size >= BTV) ? out : lgs;

    // pad head weights to a 4-aligned row stride (vectorized B path in head GEMM)
    pad_headw_kernel<<<C_, 256>>>(headw, hwp);

    embed_kernel<<<MTOT, 256>>>(idx, tok, pos, x);

    dim3 gQKV(C_ / 128, MTOT / 128, 3);                 // 384 CTAs
    dim3 gC(C_ / 128, MTOT / 128);                      // 128 CTAs
    dim3 gF(FF_ / 128, MTOT / 128);                     // 512 CTAs
    dim3 gHsw(MTOT / 128, (V_ + 127) / 128);            // head GEMM, row-fastest (L2 B reuse)
    dim3 gFA(T_ / 64, B_ * H_);                         // flash attention: 512 CTAs

    for (int l = 0; l < L_; l++) {
        const size_t oC = (size_t)l * C_;
        const size_t oCC = (size_t)l * C_ * C_;
        const size_t oCF = (size_t)l * C_ * FF_;

        layernorm_kernel<<<MTOT, 256>>>(x, ln1w + oC, ln1b + oC, h);

        gemm_qkv_tf32_kernel<<<gQKV, 128, GEMM_SMEM>>>(h, Wq + oCC, Wk + oCC, Wv + oCC,
                                                       bq + oC, bk + oC, bv + oC, q, k, v);

        flash_attn_kernel<<<gFA, 128, FLASH_SMEM>>>(q, k, v, y);

        gemm_tf32_kernel<0, true, true, false><<<gC, 128, GEMM_SMEM>>>(
            y, C_, Wo + oCC, C_, bo + oC, x, C_, x, C_, MTOT, C_, C_);

        layernorm_kernel<<<MTOT, 256>>>(x, ln2w + oC, ln2b + oC, h);

        gemm_tf32_kernel<1, true, false, false><<<gF, 128, GEMM_SMEM>>>(
            h, C_, W1 + oCF, FF_, b1 + (size_t)l * FF_, nullptr, 0, mlp, FF_, MTOT, FF_, C_);
        gemm_tf32_kernel<0, true, true, false><<<gC, 128, GEMM_SMEM>>>(
            mlp, FF_, W2 + oCF, C_, b2 + oC, x, C_, x, C_, MTOT, C_, FF_);
    }

    layernorm_kernel<<<MTOT, 256>>>(x, lnfw, lnfb, h);
    // padded-stride head GEMM: ldb = VPAD_ (mult of 4) -> 16B cp.async B loads
    gemm_tf32_kernel<0, false, false, true><<<gHsw, 128, GEMM_SMEM>>>(
        h, C_, hwp, VPAD_, nullptr, nullptr, 0, logits, V_, MTOT, V_, C_);

    nll_kernel<<<MTOT, 256>>>(logits, targets, nllbuf);
    if ((size_t)out_size == BTV + 1) {
        loss_kernel<<<1, 256>>>(nllbuf, out + BTV);
    } else if ((size_t)out_size < BTV && out_size >= 1) {
        loss_kernel<<<1, 256>>>(nllbuf, out);
    }
}

// round 10
// speedup vs baseline: 1.0727x; 1.0727x over previous
#include <cuda_runtime.h>
#include <math.h>
#include <stdint.h>

// ---------------- problem constants ----------------
#define B_ 2
#define T_ 1024
#define C_ 1024
#define H_ 16
#define HD_ 64
#define L_ 12
#define V_ 50257
#define MTOT (B_ * T_)      // 2048 token rows
#define FF_ (4 * C_)        // 4096

// ---------------- static device scratch ----------------
__device__ float g_x[MTOT * C_];
__device__ float g_h[MTOT * C_];
__device__ float g_q[MTOT * C_];
__device__ float g_k[MTOT * C_];
__device__ float g_v[MTOT * C_];
__device__ float g_y[MTOT * C_];
__device__ float g_mlp[MTOT * FF_];
__device__ float g_nll[MTOT];
__device__ float g_logits[(size_t)MTOT * V_];        // fallback if d_out can't hold logits

// ---------------- helpers ----------------
__device__ __forceinline__ float gelu_exact(float v) {
    return 0.5f * v * (1.0f + erff(v * 0.7071067811865476f));
}

__device__ __forceinline__ uint32_t f2tf32(float x) {
    uint32_t r;
    asm("cvt.rna.tf32.f32 %0, %1;" : "=r"(r) : "f"(x));
    return r;
}

__device__ __forceinline__ uint32_t smem_u32(const void* p) {
    return (uint32_t)__cvta_generic_to_shared(p);
}

#define MMA_TF32(c, a0, a1, a2, a3, b0, b1)                                  \
    asm volatile(                                                            \
        "mma.sync.aligned.m16n8k8.row.col.f32.tf32.tf32.f32 "                \
        "{%0,%1,%2,%3}, {%4,%5,%6,%7}, {%8,%9}, {%0,%1,%2,%3};\n"            \
        : "+f"((c)[0]), "+f"((c)[1]), "+f"((c)[2]), "+f"((c)[3])             \
        : "r"(a0), "r"(a1), "r"(a2), "r"(a3), "r"(b0), "r"(b1))

#define CP_ASYNC16(dst, src)                                                 \
    asm volatile("cp.async.cg.shared.global [%0], [%1], 16;"                 \
                 :: "r"(dst), "l"(src))
#define CP_COMMIT() asm volatile("cp.async.commit_group;")
#define CP_WAIT(n)  asm volatile("cp.async.wait_group %0;" :: "n"(n) : "memory")

// ---------------- embedding ----------------
__global__ void embed_kernel(const int* __restrict__ idx,
                             const float* __restrict__ tok,
                             const float* __restrict__ pos,
                             float* __restrict__ x) {
    int row = blockIdx.x;
    int t = row % T_;
    int id = idx[row];
    const float* tr = tok + (size_t)id * C_;
    const float* pr = pos + (size_t)t * C_;
    float* xr = x + (size_t)row * C_;
#pragma unroll
    for (int j = 0; j < 4; j++) {
        int c = threadIdx.x + j * 256;
        xr[c] = tr[c] + pr[c];
    }
}

// ---------------- layernorm ----------------
__global__ void layernorm_kernel(const float* __restrict__ x,
                                 const float* __restrict__ w,
                                 const float* __restrict__ b,
                                 float* __restrict__ out) {
    int row = blockIdx.x;
    int tid = threadIdx.x;
    const float* xr = x + (size_t)row * C_;
    float v[4];
    float s = 0.f;
#pragma unroll
    for (int j = 0; j < 4; j++) { v[j] = xr[tid + j * 256]; s += v[j]; }
    __shared__ float red[256];
    red[tid] = s; __syncthreads();
    for (int off = 128; off > 0; off >>= 1) {
        if (tid < off) red[tid] += red[tid + off];
        __syncthreads();
    }
    float mu = red[0] * (1.0f / C_);
    __syncthreads();
    float s2 = 0.f;
#pragma unroll
    for (int j = 0; j < 4; j++) { float d = v[j] - mu; s2 += d * d; }
    red[tid] = s2; __syncthreads();
    for (int off = 128; off > 0; off >>= 1) {
        if (tid < off) red[tid] += red[tid + off];
        __syncthreads();
    }
    float var = red[0] * (1.0f / C_);
    float rstd = rsqrtf(var + 1e-5f);
    float* orow = out + (size_t)row * C_;
#pragma unroll
    for (int j = 0; j < 4; j++) {
        int c = tid + j * 256;
        orow[c] = (v[j] - mu) * rstd * w[c] + b[c];
    }
}

// ---------------- TF32 tensor-core GEMM, cp.async 4-stage pipeline ----------------
// Templated on BM (row-tile): 128 (2 CTAs/SM) or 64 (3 CTAs/SM, 2x CTAs for
// small-grid GEMMs so all 148 SMs stay busy). Warp grid 2x2; warp tile (BM/2)x64.
#define AS_STRIDE 20
#define BS_STRIDE 136
#define GSTAGES 4
#define BS_ELEMS (16 * BS_STRIDE)
#define GEMM_SMEM(BM) (((BM) * AS_STRIDE + BS_ELEMS) * GSTAGES * 4)

template <int BM, int ACT, bool HAS_BIAS, bool HAS_RES>
__device__ __forceinline__ void gemm_body(const float* __restrict__ A, int lda,
                                          const float* __restrict__ Bm, int ldb,
                                          const float* __restrict__ bias,
                                          const float* __restrict__ resid, int ldr,
                                          float* __restrict__ Cm, int ldc,
                                          int M, int N, int K,
                                          int rowBase, int colBase) {
    constexpr int AS_ELEMS = BM * AS_STRIDE;
    constexpr int MT = BM / 32;                 // m16 tiles per warp (4 or 2)
    extern __shared__ float dsm[];
    float* As = dsm;                            // [GSTAGES][AS_ELEMS]
    float* Bs = dsm + GSTAGES * AS_ELEMS;       // [GSTAGES][BS_ELEMS]

    const int tid = threadIdx.x;
    const int lane = tid & 31, warp = tid >> 5;
    const int g = lane >> 2, tg = lane & 3;
    const int wm = warp >> 1, wn = warp & 1;    // 2x2 warp grid

    float c[MT][8][4];
#pragma unroll
    for (int i = 0; i < MT; i++)
#pragma unroll
        for (int j = 0; j < 8; j++)
#pragma unroll
            for (int r = 0; r < 4; r++) c[i][j][r] = 0.f;

    const bool vecB = ((ldb & 3) == 0) && (colBase + 128 <= N);

    auto loadA = [&](int s, int kt) {
        float* Ad = As + s * AS_ELEMS;
#pragma unroll
        for (int i = 0; i < BM / 32; i++) {
            int lin = tid + i * 128;
            int r = lin >> 2, c4 = lin & 3;
            uint32_t dst = smem_u32(&Ad[r * AS_STRIDE + c4 * 4]);
            const float* src = A + (size_t)(rowBase + r) * lda + kt + c4 * 4;
            CP_ASYNC16(dst, src);
        }
    };
    auto loadB = [&](int s, int kt) {
        float* Bd = Bs + s * BS_ELEMS;
        if (vecB) {
#pragma unroll
            for (int i = 0; i < 4; i++) {
                int lin = tid + i * 128;
                int r = lin >> 5, c4 = lin & 31;
                uint32_t dst = smem_u32(&Bd[r * BS_STRIDE + c4 * 4]);
                const float* src = Bm + (size_t)(kt + r) * ldb + colBase + c4 * 4;
                CP_ASYNC16(dst, src);
            }
        } else {
#pragma unroll
            for (int i = 0; i < 16; i++) {
                int lin = tid + i * 128;
                int r = lin >> 7, cc = lin & 127;
                int gc = colBase + cc;
                uint32_t dst = smem_u32(&Bd[r * BS_STRIDE + cc]);
                int gcs = gc < N ? gc : (N - 1);
                const float* src = Bm + (size_t)(kt + r) * ldb + gcs;
                uint32_t ssz = (gc < N) ? 4u : 0u;
                asm volatile("cp.async.ca.shared.global [%0], [%1], 4, %2;"
                             :: "r"(dst), "l"(src), "r"(ssz));
            }
        }
    };

    const int nkt = K >> 4;
#pragma unroll
    for (int s = 0; s < GSTAGES - 1; s++) {
        loadA(s, s * 16);
        loadB(s, s * 16);
        CP_COMMIT();
    }

    for (int t = 0; t < nkt; t++) {
        CP_WAIT(GSTAGES - 2);
        __syncthreads();
        int ld = t + GSTAGES - 1;
        if (ld < nkt) {
            loadA(ld & 3, ld * 16);
            loadB(ld & 3, ld * 16);
        }
        CP_COMMIT();

        const int s = t & 3;
        const float* Ap = As + s * AS_ELEMS;
        const float* Bp = Bs + s * BS_ELEMS;
#pragma unroll
        for (int k8 = 0; k8 < 16; k8 += 8) {
            uint32_t af[MT][4], bf[8][2];
#pragma unroll
            for (int mt = 0; mt < MT; mt++) {
                int mrow = wm * (BM / 2) + mt * 16 + g;
                af[mt][0] = f2tf32(Ap[mrow * AS_STRIDE + k8 + tg]);
                af[mt][1] = f2tf32(Ap[(mrow + 8) * AS_STRIDE + k8 + tg]);
                af[mt][2] = f2tf32(Ap[mrow * AS_STRIDE + k8 + tg + 4]);
                af[mt][3] = f2tf32(Ap[(mrow + 8) * AS_STRIDE + k8 + tg + 4]);
            }
#pragma unroll
            for (int nt = 0; nt < 8; nt++) {
                int ncol = wn * 64 + nt * 8 + g;
                bf[nt][0] = f2tf32(Bp[(k8 + tg) * BS_STRIDE + ncol]);
                bf[nt][1] = f2tf32(Bp[(k8 + tg + 4) * BS_STRIDE + ncol]);
            }
#pragma unroll
            for (int mt = 0; mt < MT; mt++)
#pragma unroll
                for (int nt = 0; nt < 8; nt++)
                    MMA_TF32(c[mt][nt], af[mt][0], af[mt][1], af[mt][2], af[mt][3],
                             bf[nt][0], bf[nt][1]);
        }
    }

    // ---- epilogue ----
    const bool vecC = ((ldc & 1) == 0);
#pragma unroll
    for (int mt = 0; mt < MT; mt++) {
#pragma unroll
        for (int ri = 0; ri < 2; ri++) {
            int gr = rowBase + wm * (BM / 2) + mt * 16 + g + ri * 8;
#pragma unroll
            for (int nt = 0; nt < 8; nt++) {
                int gc = colBase + wn * 64 + nt * 8 + 2 * tg;
                if (gc >= N) continue;
                bool in1 = (gc + 1) < N;
                float v0 = c[mt][nt][ri * 2 + 0];
                float v1 = c[mt][nt][ri * 2 + 1];
                if (HAS_BIAS) { v0 += bias[gc]; if (in1) v1 += bias[gc + 1]; }
                if (ACT == 1) { v0 = gelu_exact(v0); if (in1) v1 = gelu_exact(v1); }
                if (HAS_RES) {
                    v0 += resid[(size_t)gr * ldr + gc];
                    if (in1) v1 += resid[(size_t)gr * ldr + gc + 1];
                }
                float* cp = Cm + (size_t)gr * ldc + gc;
                if (vecC && in1) {
                    *reinterpret_cast<float2*>(cp) = make_float2(v0, v1);
                } else {
                    cp[0] = v0;
                    if (in1) cp[1] = v1;
                }
            }
        }
    }
}

template <int ACT, bool HAS_BIAS, bool HAS_RES, bool SWAP>
__global__ void __launch_bounds__(128, 2)
gemm_tf32_kernel(const float* __restrict__ A, int lda,
                 const float* __restrict__ Bm, int ldb,
                 const float* __restrict__ bias,
                 const float* __restrict__ resid, int ldr,
                 float* __restrict__ Cm, int ldc,
                 int M, int N, int K) {
    int rowBase = (SWAP ? blockIdx.x : blockIdx.y) * 128;
    int colBase = (SWAP ? blockIdx.y : blockIdx.x) * 128;
    gemm_body<128, ACT, HAS_BIAS, HAS_RES>(A, lda, Bm, ldb, bias, resid, ldr,
                                           Cm, ldc, M, N, K, rowBase, colBase);
}

// BM=64 variant for small-grid GEMMs (Wo, FC2): 256 CTAs, 3 CTAs/SM
template <int ACT, bool HAS_BIAS, bool HAS_RES>
__global__ void __launch_bounds__(128, 3)
gemm64_tf32_kernel(const float* __restrict__ A, int lda,
                   const float* __restrict__ Bm, int ldb,
                   const float* __restrict__ bias,
                   const float* __restrict__ resid, int ldr,
                   float* __restrict__ Cm, int ldc,
                   int M, int N, int K) {
    int rowBase = blockIdx.y * 64;
    int colBase = blockIdx.x * 128;
    gemm_body<64, ACT, HAS_BIAS, HAS_RES>(A, lda, Bm, ldb, bias, resid, ldr,
                                          Cm, ldc, M, N, K, rowBase, colBase);
}

// fused QKV: blockIdx.z selects which projection
__global__ void __launch_bounds__(128, 2)
gemm_qkv_tf32_kernel(const float* __restrict__ h,
                     const float* __restrict__ Wq, const float* __restrict__ Wk,
                     const float* __restrict__ Wv,
                     const float* __restrict__ bq, const float* __restrict__ bk,
                     const float* __restrict__ bv,
                     float* __restrict__ qo, float* __restrict__ ko,
                     float* __restrict__ vo) {
    const float* Bm; const float* bias; float* Cm;
    if (blockIdx.z == 0)      { Bm = Wq; bias = bq; Cm = qo; }
    else if (blockIdx.z == 1) { Bm = Wk; bias = bk; Cm = ko; }
    else                      { Bm = Wv; bias = bv; Cm = vo; }
    gemm_body<128, 0, true, false>(h, C_, Bm, C_, bias, nullptr, 0, Cm, C_, MTOT, C_, C_,
                                   blockIdx.y * 128, blockIdx.x * 128);
}

// ---------------- fused flash attention (S and PV both on TF32 MMA) ----------------
#define QP 68
#define KP 68
#define VP 72
#define PP 68
#define FLASH_SMEM ((64 * QP + 2 * 64 * KP + 2 * 64 * VP + 64 * PP) * 4)

__global__ void __launch_bounds__(128, 2)
flash_attn_kernel(const float* __restrict__ q, const float* __restrict__ k,
                  const float* __restrict__ v, float* __restrict__ y) {
    extern __shared__ float sm[];
    float* Qs = sm;                       // [m][d]
    float* Ks = Qs + 64 * QP;             // 2 x [n][d]
    float* Vs = Ks + 2 * 64 * KP;         // 2 x [n][d]
    float* Ps = Vs + 2 * 64 * VP;         // [m][n]

    const int tid = threadIdx.x;
    const int lane = tid & 31, warp = tid >> 5;
    const int g = lane >> 2, tg = lane & 3;
    const int z = blockIdx.y;
    const int b = z >> 4, h = z & 15;
    const int qt = (T_ / 64 - 1) - blockIdx.x;   // heavy CTAs first
    const int rowBase = qt * 64;

    const float* qb = q + (size_t)b * T_ * C_ + h * HD_;
    const float* kb = k + (size_t)b * T_ * C_ + h * HD_;
    const float* vb = v + (size_t)b * T_ * C_ + h * HD_;
    float* yb = y + (size_t)b * T_ * C_ + h * HD_;

    auto loadKV = [&](int s, int kt) {
        const float* kbt = kb + (size_t)kt * 64 * C_;
        const float* vbt = vb + (size_t)kt * 64 * C_;
        float* Kd = Ks + s * 64 * KP;
        float* Vd = Vs + s * 64 * VP;
#pragma unroll
        for (int i = 0; i < 8; i++) {
            int lin = tid + i * 128;
            int n = lin >> 4, d4 = lin & 15;
            CP_ASYNC16(smem_u32(&Kd[n * KP + d4 * 4]), kbt + (size_t)n * C_ + d4 * 4);
        }
#pragma unroll
        for (int i = 0; i < 8; i++) {
            int lin = tid + i * 128;
            int n = lin >> 4, d4 = lin & 15;
            CP_ASYNC16(smem_u32(&Vd[n * VP + d4 * 4]), vbt + (size_t)n * C_ + d4 * 4);
        }
    };

    // Q tile (once) + first KV stage in one group
#pragma unroll
    for (int i = 0; i < 8; i++) {
        int lin = tid + i * 128;
        int mm = lin >> 4, d4 = lin & 15;
        CP_ASYNC16(smem_u32(&Qs[mm * QP + d4 * 4]), qb + (size_t)(rowBase + mm) * C_ + d4 * 4);
    }
    loadKV(0, 0);
    CP_COMMIT();

    const int r0 = warp * 16 + g, r1 = r0 + 8;   // rows owned (S and O share layout)
    float m0 = -INFINITY, m1 = -INFINITY, l0 = 0.f, l1 = 0.f;
    float of[8][4];
#pragma unroll
    for (int nt = 0; nt < 8; nt++)
#pragma unroll
        for (int r = 0; r < 4; r++) of[nt][r] = 0.f;

    for (int kt = 0; kt <= qt; kt++) {
        const int s = kt & 1;
        CP_WAIT(0);
        __syncthreads();
        if (kt < qt) loadKV(s ^ 1, kt + 1);
        CP_COMMIT();

        // ---- S = Q.K^T (TF32 MMA), K natural [n][d] read K-major ----
        const float* Kp = Ks + s * 64 * KP;
        float sf[8][4];
#pragma unroll
        for (int nt = 0; nt < 8; nt++)
#pragma unroll
            for (int r = 0; r < 4; r++) sf[nt][r] = 0.f;
#pragma unroll
        for (int k8 = 0; k8 < 64; k8 += 8) {
            uint32_t a0 = f2tf32(Qs[r0 * QP + k8 + tg]);
            uint32_t a1 = f2tf32(Qs[r1 * QP + k8 + tg]);
            uint32_t a2 = f2tf32(Qs[r0 * QP + k8 + tg + 4]);
            uint32_t a3 = f2tf32(Qs[r1 * QP + k8 + tg + 4]);
#pragma unroll
            for (int nt = 0; nt < 8; nt++) {
                int ncol = nt * 8 + g;
                uint32_t b0 = f2tf32(Kp[ncol * KP + k8 + tg]);
                uint32_t b1 = f2tf32(Kp[ncol * KP + k8 + tg + 4]);
                MMA_TF32(sf[nt], a0, a1, a2, a3, b0, b1);
            }
        }
#pragma unroll
        for (int nt = 0; nt < 8; nt++)
#pragma unroll
            for (int r = 0; r < 4; r++) sf[nt][r] *= 0.125f;   // 1/sqrt(HD)

        // ---- causal mask (diag tile only) ----
        if (kt == qt) {
            int gr0 = rowBase + r0, gr1 = rowBase + r1;
            int cb = kt * 64;
#pragma unroll
            for (int nt = 0; nt < 8; nt++) {
                int c0 = cb + nt * 8 + 2 * tg, c1 = c0 + 1;
                if (c0 > gr0) sf[nt][0] = -1e30f;
                if (c1 > gr0) sf[nt][1] = -1e30f;
                if (c0 > gr1) sf[nt][2] = -1e30f;
                if (c1 > gr1) sf[nt][3] = -1e30f;
            }
        }

        // ---- online softmax (registers only; quad-shuffle reductions) ----
        float mx0 = -INFINITY, mx1 = -INFINITY;
#pragma unroll
        for (int nt = 0; nt < 8; nt++) {
            mx0 = fmaxf(mx0, fmaxf(sf[nt][0], sf[nt][1]));
            mx1 = fmaxf(mx1, fmaxf(sf[nt][2], sf[nt][3]));
        }
        mx0 = fmaxf(mx0, __shfl_xor_sync(0xFFFFFFFF, mx0, 1));
        mx0 = fmaxf(mx0, __shfl_xor_sync(0xFFFFFFFF, mx0, 2));
        mx1 = fmaxf(mx1, __shfl_xor_sync(0xFFFFFFFF, mx1, 1));
        mx1 = fmaxf(mx1, __shfl_xor_sync(0xFFFFFFFF, mx1, 2));

        float mn0 = fmaxf(m0, mx0), mn1 = fmaxf(m1, mx1);
        float a0s = __expf(m0 - mn0), a1s = __expf(m1 - mn1);

        float rs0 = 0.f, rs1 = 0.f;
#pragma unroll
        for (int nt = 0; nt < 8; nt++) {
            sf[nt][0] = __expf(sf[nt][0] - mn0);
            sf[nt][1] = __expf(sf[nt][1] - mn0);
            sf[nt][2] = __expf(sf[nt][2] - mn1);
            sf[nt][3] = __expf(sf[nt][3] - mn1);
            rs0 += sf[nt][0] + sf[nt][1];
            rs1 += sf[nt][2] + sf[nt][3];
        }
        rs0 += __shfl_xor_sync(0xFFFFFFFF, rs0, 1);
        rs0 += __shfl_xor_sync(0xFFFFFFFF, rs0, 2);
        rs1 += __shfl_xor_sync(0xFFFFFFFF, rs1, 1);
        rs1 += __shfl_xor_sync(0xFFFFFFFF, rs1, 2);

        m0 = mn0; m1 = mn1;
        l0 = l0 * a0s + rs0;
        l1 = l1 * a1s + rs1;

        // ---- P to smem (only this warp's rows; warp-local reuse) ----
#pragma unroll
        for (int nt = 0; nt < 8; nt++) {
            int cc = nt * 8 + 2 * tg;
            *reinterpret_cast<float2*>(&Ps[r0 * PP + cc]) = make_float2(sf[nt][0], sf[nt][1]);
            *reinterpret_cast<float2*>(&Ps[r1 * PP + cc]) = make_float2(sf[nt][2], sf[nt][3]);
        }
        __syncwarp();

        // ---- O = O*alpha + P.V (TF32 MMA), V natural [n][d] ----
#pragma unroll
        for (int nt = 0; nt < 8; nt++) {
            of[nt][0] *= a0s; of[nt][1] *= a0s;
            of[nt][2] *= a1s; of[nt][3] *= a1s;
        }
        const float* Vp = Vs + s * 64 * VP;
#pragma unroll
        for (int k8 = 0; k8 < 64; k8 += 8) {
            uint32_t a0 = f2tf32(Ps[r0 * PP + k8 + tg]);
            uint32_t a1 = f2tf32(Ps[r1 * PP + k8 + tg]);
            uint32_t a2 = f2tf32(Ps[r0 * PP + k8 + tg + 4]);
            uint32_t a3 = f2tf32(Ps[r1 * PP + k8 + tg + 4]);
#pragma unroll
            for (int nt = 0; nt < 8; nt++) {
                int ncol = nt * 8 + g;
                uint32_t b0 = f2tf32(Vp[(k8 + tg) * VP + ncol]);
                uint32_t b1 = f2tf32(Vp[(k8 + tg + 4) * VP + ncol]);
                MMA_TF32(of[nt], a0, a1, a2, a3, b0, b1);
            }
        }
    }

    // ---- epilogue: y = O / l (fragment layout direct to gmem) ----
    float inv0 = 1.0f / l0, inv1 = 1.0f / l1;
    float* yr0 = yb + (size_t)(rowBase + r0) * C_;
    float* yr1 = yb + (size_t)(rowBase + r1) * C_;
#pragma unroll
    for (int nt = 0; nt < 8; nt++) {
        int cc = nt * 8 + 2 * tg;
        *reinterpret_cast<float2*>(yr0 + cc) = make_float2(of[nt][0] * inv0, of[nt][1] * inv0);
        *reinterpret_cast<float2*>(yr1 + cc) = make_float2(of[nt][2] * inv1, of[nt][3] * inv1);
    }
}

// ---------------- per-row NLL over V (single-pass online) ----------------
__global__ void nll_kernel(const float* __restrict__ logits,
                           const int* __restrict__ targets,
                           float* __restrict__ nll) {
    int row = blockIdx.x;
    const float* p = logits + (size_t)row * V_;
    int tid = threadIdx.x;
    float m = -INFINITY, s = 0.f;
    for (int c = tid; c < V_; c += 256) {
        float v = p[c];
        if (v <= m) {
            s += expf(v - m);
        } else {
            s = s * expf(m - v) + 1.0f;
            m = v;
        }
    }
    __shared__ float rm[256], rs[256];
    rm[tid] = m; rs[tid] = s; __syncthreads();
    for (int off = 128; off > 0; off >>= 1) {
        if (tid < off) {
            float m1 = rm[tid], s1 = rs[tid];
            float m2 = rm[tid + off], s2 = rs[tid + off];
            float M = fmaxf(m1, m2);
            rm[tid] = M;
            rs[tid] = s1 * expf(m1 - M) + s2 * expf(m2 - M);
        }
        __syncthreads();
    }
    if (tid == 0) {
        float lt = p[targets[row]];
        nll[row] = -(lt - rm[0] - logf(rs[0]));
    }
}

__global__ void loss_kernel(const float* __restrict__ nll, float* __restrict__ out) {
    __shared__ float red[256];
    int tid = threadIdx.x;
    float s = 0.f;
    for (int c = tid; c < MTOT; c += 256) s += nll[c];
    red[tid] = s; __syncthreads();
    for (int off = 128; off > 0; off >>= 1) {
        if (tid < off) red[tid] += red[tid + off];
        __syncthreads();
    }
    if (tid == 0) out[0] = red[0] * (1.0f / MTOT);
}

// ---------------- host launcher ----------------
extern "C" void kernel_launch(void* const* d_in, const int* in_sizes, int n_in,
                              void* d_out, int out_size) {
    const int*   idx     = (const int*)d_in[0];
    const int*   targets = (const int*)d_in[1];
    const float* tok     = (const float*)d_in[2];
    const float* pos     = (const float*)d_in[3];
    const float* ln1w    = (const float*)d_in[4];
    const float* ln1b    = (const float*)d_in[5];
    const float* ln2w    = (const float*)d_in[6];
    const float* ln2b    = (const float*)d_in[7];
    const float* Wq      = (const float*)d_in[8];
    const float* bq      = (const float*)d_in[9];
    const float* Wk      = (const float*)d_in[10];
    const float* bk      = (const float*)d_in[11];
    const float* Wv      = (const float*)d_in[12];
    const float* bv      = (const float*)d_in[13];
    const float* Wo      = (const float*)d_in[14];
    const float* bo      = (const float*)d_in[15];
    const float* W1      = (const float*)d_in[16];
    const float* b1      = (const float*)d_in[17];
    const float* W2      = (const float*)d_in[18];
    const float* b2      = (const float*)d_in[19];
    const float* lnfw    = (const float*)d_in[20];
    const float* lnfb    = (const float*)d_in[21];
    const float* headw   = (const float*)d_in[22];
    float* out = (float*)d_out;

    float *x, *h, *q, *k, *v, *y, *mlp, *nllbuf, *lgs;
    cudaGetSymbolAddress((void**)&x, g_x);
    cudaGetSymbolAddress((void**)&h, g_h);
    cudaGetSymbolAddress((void**)&q, g_q);
    cudaGetSymbolAddress((void**)&k, g_k);
    cudaGetSymbolAddress((void**)&v, g_v);
    cudaGetSymbolAddress((void**)&y, g_y);
    cudaGetSymbolAddress((void**)&mlp, g_mlp);
    cudaGetSymbolAddress((void**)&nllbuf, g_nll);
    cudaGetSymbolAddress((void**)&lgs, g_logits);

    cudaFuncSetAttribute(flash_attn_kernel,
                         cudaFuncAttributeMaxDynamicSharedMemorySize, FLASH_SMEM);
    cudaFuncSetAttribute(gemm_qkv_tf32_kernel,
                         cudaFuncAttributeMaxDynamicSharedMemorySize, GEMM_SMEM(128));
    cudaFuncSetAttribute(gemm_tf32_kernel<1, true, false, false>,
                         cudaFuncAttributeMaxDynamicSharedMemorySize, GEMM_SMEM(128));
    cudaFuncSetAttribute(gemm_tf32_kernel<0, false, false, true>,
                         cudaFuncAttributeMaxDynamicSharedMemorySize, GEMM_SMEM(128));
    cudaFuncSetAttribute(gemm64_tf32_kernel<0, true, true>,
                         cudaFuncAttributeMaxDynamicSharedMemorySize, GEMM_SMEM(64));

    const size_t BTV = (size_t)MTOT * V_;
    float* logits = ((size_t)out_size >= BTV) ? out : lgs;

    embed_kernel<<<MTOT, 256>>>(idx, tok, pos, x);

    dim3 gQKV(C_ / 128, MTOT / 128, 3);                 // 384 CTAs
    dim3 gC64(C_ / 128, MTOT / 64);                     // 256 CTAs (Wo, FC2)
    dim3 gF(FF_ / 128, MTOT / 128);                     // 512 CTAs
    dim3 gHsw(MTOT / 128, (V_ + 127) / 128);            // head GEMM, row-fastest (L2 B reuse)
    dim3 gFA(T_ / 64, B_ * H_);                         // flash attention: 512 CTAs

    for (int l = 0; l < L_; l++) {
        const size_t oC = (size_t)l * C_;
        const size_t oCC = (size_t)l * C_ * C_;
        const size_t oCF = (size_t)l * C_ * FF_;

        layernorm_kernel<<<MTOT, 256>>>(x, ln1w + oC, ln1b + oC, h);

        gemm_qkv_tf32_kernel<<<gQKV, 128, GEMM_SMEM(128)>>>(h, Wq + oCC, Wk + oCC, Wv + oCC,
                                                            bq + oC, bk + oC, bv + oC,
                                                            q, k, v);

        flash_attn_kernel<<<gFA, 128, FLASH_SMEM>>>(q, k, v, y);

        gemm64_tf32_kernel<0, true, true><<<gC64, 128, GEMM_SMEM(64)>>>(
            y, C_, Wo + oCC, C_, bo + oC, x, C_, x, C_, MTOT, C_, C_);

        layernorm_kernel<<<MTOT, 256>>>(x, ln2w + oC, ln2b + oC, h);

        gemm_tf32_kernel<1, true, false, false><<<gF, 128, GEMM_SMEM(128)>>>(
            h, C_, W1 + oCF, FF_, b1 + (size_t)l * FF_, nullptr, 0, mlp, FF_, MTOT, FF_, C_);
        gemm64_tf32_kernel<0, true, true><<<gC64, 128, GEMM_SMEM(64)>>>(
            mlp, FF_, W2 + oCF, C_, b2 + oC, x, C_, x, C_, MTOT, C_, FF_);
    }

    layernorm_kernel<<<MTOT, 256>>>(x, lnfw, lnfb, h);
    gemm_tf32_kernel<0, false, false, true><<<gHsw, 128, GEMM_SMEM(128)>>>(
        h, C_, headw, V_, nullptr, nullptr, 0, logits, V_, MTOT, V_, C_);

    nll_kernel<<<MTOT, 256>>>(logits, targets, nllbuf);
    if ((size_t)out_size == BTV + 1) {
        loss_kernel<<<1, 256>>>(nllbuf, out + BTV);
    } else if ((size_t)out_size < BTV && out_size >= 1) {
        loss_kernel<<<1, 256>>>(nllbuf, out);
    }
}

// round 11
// speedup vs baseline: 1.0836x; 1.0101x over previous
#include <cuda_runtime.h>
#include <math.h>
#include <stdint.h>

// ---------------- problem constants ----------------
#define B_ 2
#define T_ 1024
#define C_ 1024
#define H_ 16
#define HD_ 64
#define L_ 12
#define V_ 50257
#define MTOT (B_ * T_)      // 2048 token rows
#define FF_ (4 * C_)        // 4096

// ---------------- static device scratch ----------------
__device__ float g_x[MTOT * C_];
__device__ float g_h[MTOT * C_];
__device__ float g_q[MTOT * C_];
__device__ float g_k[MTOT * C_];
__device__ float g_v[MTOT * C_];
__device__ float g_y[MTOT * C_];
__device__ float g_mlp[MTOT * FF_];
__device__ float g_nll[MTOT];
__device__ float g_logits[(size_t)MTOT * V_];        // fallback if d_out can't hold logits

// ---------------- helpers ----------------
__device__ __forceinline__ float gelu_exact(float v) {
    return 0.5f * v * (1.0f + erff(v * 0.7071067811865476f));
}

__device__ __forceinline__ uint32_t f2tf32(float x) {
    uint32_t r;
    asm("cvt.rna.tf32.f32 %0, %1;" : "=r"(r) : "f"(x));
    return r;
}

__device__ __forceinline__ uint32_t smem_u32(const void* p) {
    return (uint32_t)__cvta_generic_to_shared(p);
}

#define MMA_TF32(c, a0, a1, a2, a3, b0, b1)                                  \
    asm volatile(                                                            \
        "mma.sync.aligned.m16n8k8.row.col.f32.tf32.tf32.f32 "                \
        "{%0,%1,%2,%3}, {%4,%5,%6,%7}, {%8,%9}, {%0,%1,%2,%3};\n"            \
        : "+f"((c)[0]), "+f"((c)[1]), "+f"((c)[2]), "+f"((c)[3])             \
        : "r"(a0), "r"(a1), "r"(a2), "r"(a3), "r"(b0), "r"(b1))

#define CP_ASYNC16(dst, src)                                                 \
    asm volatile("cp.async.cg.shared.global [%0], [%1], 16;"                 \
                 :: "r"(dst), "l"(src))
#define CP_COMMIT() asm volatile("cp.async.commit_group;")

// ---------------- embedding ----------------
__global__ void embed_kernel(const int* __restrict__ idx,
                             const float* __restrict__ tok,
                             const float* __restrict__ pos,
                             float* __restrict__ x) {
    int row = blockIdx.x;
    int t = row % T_;
    int id = idx[row];
    const float* tr = tok + (size_t)id * C_;
    const float* pr = pos + (size_t)t * C_;
    float* xr = x + (size_t)row * C_;
#pragma unroll
    for (int j = 0; j < 4; j++) {
        int c = threadIdx.x + j * 256;
        xr[c] = tr[c] + pr[c];
    }
}

// ---------------- layernorm ----------------
__global__ void layernorm_kernel(const float* __restrict__ x,
                                 const float* __restrict__ w,
                                 const float* __restrict__ b,
                                 float* __restrict__ out) {
    int row = blockIdx.x;
    int tid = threadIdx.x;
    const float* xr = x + (size_t)row * C_;
    float v[4];
    float s = 0.f;
#pragma unroll
    for (int j = 0; j < 4; j++) { v[j] = xr[tid + j * 256]; s += v[j]; }
    __shared__ float red[256];
    red[tid] = s; __syncthreads();
    for (int off = 128; off > 0; off >>= 1) {
        if (tid < off) red[tid] += red[tid + off];
        __syncthreads();
    }
    float mu = red[0] * (1.0f / C_);
    __syncthreads();
    float s2 = 0.f;
#pragma unroll
    for (int j = 0; j < 4; j++) { float d = v[j] - mu; s2 += d * d; }
    red[tid] = s2; __syncthreads();
    for (int off = 128; off > 0; off >>= 1) {
        if (tid < off) red[tid] += red[tid + off];
        __syncthreads();
    }
    float var = red[0] * (1.0f / C_);
    float rstd = rsqrtf(var + 1e-5f);
    float* orow = out + (size_t)row * C_;
#pragma unroll
    for (int j = 0; j < 4; j++) {
        int c = tid + j * 256;
        orow[c] = (v[j] - mu) * rstd * w[c] + b[c];
    }
}

// ---------------- TF32 tensor-core GEMM, cp.async multi-stage pipeline ----------------
// BM=128/STAGES=4 (2 CTAs/SM) or BM=64/STAGES=5 (3 CTAs/SM). Warp grid 2x2;
// warp tile (BM/2)x64. Accumulation order over k identical for both variants.
#define AS_STRIDE 20
#define BS_STRIDE 136
#define BS_ELEMS (16 * BS_STRIDE)
#define GEMM_SMEM(BM, ST) (((BM) * AS_STRIDE + BS_ELEMS) * (ST) * 4)

template <int BM, int STAGES, int ACT, bool HAS_BIAS, bool HAS_RES>
__device__ __forceinline__ void gemm_body(const float* __restrict__ A, int lda,
                                          const float* __restrict__ Bm, int ldb,
                                          const float* __restrict__ bias,
                                          const float* __restrict__ resid, int ldr,
                                          float* __restrict__ Cm, int ldc,
                                          int M, int N, int K,
                                          int rowBase, int colBase) {
    constexpr int AS_ELEMS = BM * AS_STRIDE;
    constexpr int MT = BM / 32;                 // m16 tiles per warp
    extern __shared__ float dsm[];
    float* As = dsm;                            // [STAGES][AS_ELEMS]
    float* Bs = dsm + STAGES * AS_ELEMS;        // [STAGES][BS_ELEMS]

    const int tid = threadIdx.x;
    const int lane = tid & 31, warp = tid >> 5;
    const int g = lane >> 2, tg = lane & 3;
    const int wm = warp >> 1, wn = warp & 1;    // 2x2 warp grid

    float c[MT][8][4];
#pragma unroll
    for (int i = 0; i < MT; i++)
#pragma unroll
        for (int j = 0; j < 8; j++)
#pragma unroll
            for (int r = 0; r < 4; r++) c[i][j][r] = 0.f;

    const bool vecB = ((ldb & 3) == 0) && (colBase + 128 <= N);

    auto loadA = [&](int s, int kt) {
        float* Ad = As + s * AS_ELEMS;
#pragma unroll
        for (int i = 0; i < BM / 32; i++) {
            int lin = tid + i * 128;
            int r = lin >> 2, c4 = lin & 3;
            uint32_t dst = smem_u32(&Ad[r * AS_STRIDE + c4 * 4]);
            const float* src = A + (size_t)(rowBase + r) * lda + kt + c4 * 4;
            CP_ASYNC16(dst, src);
        }
    };
    auto loadB = [&](int s, int kt) {
        float* Bd = Bs + s * BS_ELEMS;
        if (vecB) {
#pragma unroll
            for (int i = 0; i < 4; i++) {
                int lin = tid + i * 128;
                int r = lin >> 5, c4 = lin & 31;
                uint32_t dst = smem_u32(&Bd[r * BS_STRIDE + c4 * 4]);
                const float* src = Bm + (size_t)(kt + r) * ldb + colBase + c4 * 4;
                CP_ASYNC16(dst, src);
            }
        } else {
#pragma unroll
            for (int i = 0; i < 16; i++) {
                int lin = tid + i * 128;
                int r = lin >> 7, cc = lin & 127;
                int gc = colBase + cc;
                uint32_t dst = smem_u32(&Bd[r * BS_STRIDE + cc]);
                int gcs = gc < N ? gc : (N - 1);
                const float* src = Bm + (size_t)(kt + r) * ldb + gcs;
                uint32_t ssz = (gc < N) ? 4u : 0u;
                asm volatile("cp.async.ca.shared.global [%0], [%1], 4, %2;"
                             :: "r"(dst), "l"(src), "r"(ssz));
            }
        }
    };

    const int nkt = K >> 4;
#pragma unroll
    for (int s = 0; s < STAGES - 1; s++) {
        loadA(s, s * 16);
        loadB(s, s * 16);
        CP_COMMIT();
    }

    int cs = 0;   // compute stage ring index
    int ls = STAGES - 1;   // load stage ring index
    for (int t = 0; t < nkt; t++) {
        asm volatile("cp.async.wait_group %0;" :: "n"(STAGES - 2) : "memory");
        __syncthreads();
        int ld = t + STAGES - 1;
        if (ld < nkt) {
            loadA(ls, ld * 16);
            loadB(ls, ld * 16);
        }
        CP_COMMIT();
        if (++ls == STAGES) ls = 0;

        const float* Ap = As + cs * AS_ELEMS;
        const float* Bp = Bs + cs * BS_ELEMS;
        if (++cs == STAGES) cs = 0;
#pragma unroll
        for (int k8 = 0; k8 < 16; k8 += 8) {
            uint32_t af[MT][4], bf[8][2];
#pragma unroll
            for (int mt = 0; mt < MT; mt++) {
                int mrow = wm * (BM / 2) + mt * 16 + g;
                af[mt][0] = f2tf32(Ap[mrow * AS_STRIDE + k8 + tg]);
                af[mt][1] = f2tf32(Ap[(mrow + 8) * AS_STRIDE + k8 + tg]);
                af[mt][2] = f2tf32(Ap[mrow * AS_STRIDE + k8 + tg + 4]);
                af[mt][3] = f2tf32(Ap[(mrow + 8) * AS_STRIDE + k8 + tg + 4]);
            }
#pragma unroll
            for (int nt = 0; nt < 8; nt++) {
                int ncol = wn * 64 + nt * 8 + g;
                bf[nt][0] = f2tf32(Bp[(k8 + tg) * BS_STRIDE + ncol]);
                bf[nt][1] = f2tf32(Bp[(k8 + tg + 4) * BS_STRIDE + ncol]);
            }
#pragma unroll
            for (int mt = 0; mt < MT; mt++)
#pragma unroll
                for (int nt = 0; nt < 8; nt++)
                    MMA_TF32(c[mt][nt], af[mt][0], af[mt][1], af[mt][2], af[mt][3],
                             bf[nt][0], bf[nt][1]);
        }
    }

    // ---- epilogue ----
    const bool vecC = ((ldc & 1) == 0);
#pragma unroll
    for (int mt = 0; mt < MT; mt++) {
#pragma unroll
        for (int ri = 0; ri < 2; ri++) {
            int gr = rowBase + wm * (BM / 2) + mt * 16 + g + ri * 8;
#pragma unroll
            for (int nt = 0; nt < 8; nt++) {
                int gc = colBase + wn * 64 + nt * 8 + 2 * tg;
                if (gc >= N) continue;
                bool in1 = (gc + 1) < N;
                float v0 = c[mt][nt][ri * 2 + 0];
                float v1 = c[mt][nt][ri * 2 + 1];
                if (HAS_BIAS) { v0 += bias[gc]; if (in1) v1 += bias[gc + 1]; }
                if (ACT == 1) { v0 = gelu_exact(v0); if (in1) v1 = gelu_exact(v1); }
                if (HAS_RES) {
                    v0 += resid[(size_t)gr * ldr + gc];
                    if (in1) v1 += resid[(size_t)gr * ldr + gc + 1];
                }
                float* cp = Cm + (size_t)gr * ldc + gc;
                if (vecC && in1) {
                    *reinterpret_cast<float2*>(cp) = make_float2(v0, v1);
                } else {
                    cp[0] = v0;
                    if (in1) cp[1] = v1;
                }
            }
        }
    }
}

// BM=128, 4-stage (head GEMM only; 2 CTAs/SM)
template <int ACT, bool HAS_BIAS, bool HAS_RES, bool SWAP>
__global__ void __launch_bounds__(128, 2)
gemm_tf32_kernel(const float* __restrict__ A, int lda,
                 const float* __restrict__ Bm, int ldb,
                 const float* __restrict__ bias,
                 const float* __restrict__ resid, int ldr,
                 float* __restrict__ Cm, int ldc,
                 int M, int N, int K) {
    int rowBase = (SWAP ? blockIdx.x : blockIdx.y) * 128;
    int colBase = (SWAP ? blockIdx.y : blockIdx.x) * 128;
    gemm_body<128, 4, ACT, HAS_BIAS, HAS_RES>(A, lda, Bm, ldb, bias, resid, ldr,
                                              Cm, ldc, M, N, K, rowBase, colBase);
}

// BM=64, 5-stage (all layer GEMMs; 3 CTAs/SM)
template <int ACT, bool HAS_BIAS, bool HAS_RES>
__global__ void __launch_bounds__(128, 3)
gemm64_tf32_kernel(const float* __restrict__ A, int lda,
                   const float* __restrict__ Bm, int ldb,
                   const float* __restrict__ bias,
                   const float* __restrict__ resid, int ldr,
                   float* __restrict__ Cm, int ldc,
                   int M, int N, int K) {
    int rowBase = blockIdx.y * 64;
    int colBase = blockIdx.x * 128;
    gemm_body<64, 5, ACT, HAS_BIAS, HAS_RES>(A, lda, Bm, ldb, bias, resid, ldr,
                                             Cm, ldc, M, N, K, rowBase, colBase);
}

// fused QKV (BM=64): blockIdx.z selects which projection
__global__ void __launch_bounds__(128, 3)
gemm_qkv_tf32_kernel(const float* __restrict__ h,
                     const float* __restrict__ Wq, const float* __restrict__ Wk,
                     const float* __restrict__ Wv,
                     const float* __restrict__ bq, const float* __restrict__ bk,
                     const float* __restrict__ bv,
                     float* __restrict__ qo, float* __restrict__ ko,
                     float* __restrict__ vo) {
    const float* Bm; const float* bias; float* Cm;
    if (blockIdx.z == 0)      { Bm = Wq; bias = bq; Cm = qo; }
    else if (blockIdx.z == 1) { Bm = Wk; bias = bk; Cm = ko; }
    else                      { Bm = Wv; bias = bv; Cm = vo; }
    gemm_body<64, 5, 0, true, false>(h, C_, Bm, C_, bias, nullptr, 0, Cm, C_,
                                     MTOT, C_, C_, blockIdx.y * 64, blockIdx.x * 128);
}

// ---------------- fused flash attention (S and PV both on TF32 MMA) ----------------
#define QP 68
#define KP 68
#define VP 72
#define PP 68
#define FLASH_SMEM ((64 * QP + 2 * 64 * KP + 2 * 64 * VP + 64 * PP) * 4)

__global__ void __launch_bounds__(128, 2)
flash_attn_kernel(const float* __restrict__ q, const float* __restrict__ k,
                  const float* __restrict__ v, float* __restrict__ y) {
    extern __shared__ float sm[];
    float* Qs = sm;                       // [m][d]
    float* Ks = Qs + 64 * QP;             // 2 x [n][d]
    float* Vs = Ks + 2 * 64 * KP;         // 2 x [n][d]
    float* Ps = Vs + 2 * 64 * VP;         // [m][n]

    const int tid = threadIdx.x;
    const int lane = tid & 31, warp = tid >> 5;
    const int g = lane >> 2, tg = lane & 3;
    const int z = blockIdx.y;
    const int b = z >> 4, h = z & 15;
    const int qt = (T_ / 64 - 1) - blockIdx.x;   // heavy CTAs first
    const int rowBase = qt * 64;

    const float* qb = q + (size_t)b * T_ * C_ + h * HD_;
    const float* kb = k + (size_t)b * T_ * C_ + h * HD_;
    const float* vb = v + (size_t)b * T_ * C_ + h * HD_;
    float* yb = y + (size_t)b * T_ * C_ + h * HD_;

    auto loadKV = [&](int s, int kt) {
        const float* kbt = kb + (size_t)kt * 64 * C_;
        const float* vbt = vb + (size_t)kt * 64 * C_;
        float* Kd = Ks + s * 64 * KP;
        float* Vd = Vs + s * 64 * VP;
#pragma unroll
        for (int i = 0; i < 8; i++) {
            int lin = tid + i * 128;
            int n = lin >> 4, d4 = lin & 15;
            CP_ASYNC16(smem_u32(&Kd[n * KP + d4 * 4]), kbt + (size_t)n * C_ + d4 * 4);
        }
#pragma unroll
        for (int i = 0; i < 8; i++) {
            int lin = tid + i * 128;
            int n = lin >> 4, d4 = lin & 15;
            CP_ASYNC16(smem_u32(&Vd[n * VP + d4 * 4]), vbt + (size_t)n * C_ + d4 * 4);
        }
    };

    // Q tile (once) + first KV stage in one group
#pragma unroll
    for (int i = 0; i < 8; i++) {
        int lin = tid + i * 128;
        int mm = lin >> 4, d4 = lin & 15;
        CP_ASYNC16(smem_u32(&Qs[mm * QP + d4 * 4]), qb + (size_t)(rowBase + mm) * C_ + d4 * 4);
    }
    loadKV(0, 0);
    CP_COMMIT();

    const int r0 = warp * 16 + g, r1 = r0 + 8;   // rows owned (S and O share layout)
    float m0 = -INFINITY, m1 = -INFINITY, l0 = 0.f, l1 = 0.f;
    float of[8][4];
#pragma unroll
    for (int nt = 0; nt < 8; nt++)
#pragma unroll
        for (int r = 0; r < 4; r++) of[nt][r] = 0.f;

    for (int kt = 0; kt <= qt; kt++) {
        const int s = kt & 1;
        asm volatile("cp.async.wait_group 0;" ::: "memory");
        __syncthreads();
        if (kt < qt) loadKV(s ^ 1, kt + 1);
        CP_COMMIT();

        // ---- S = Q.K^T (TF32 MMA), K natural [n][d] read K-major ----
        const float* Kp = Ks + s * 64 * KP;
        float sf[8][4];
#pragma unroll
        for (int nt = 0; nt < 8; nt++)
#pragma unroll
            for (int r = 0; r < 4; r++) sf[nt][r] = 0.f;
#pragma unroll
        for (int k8 = 0; k8 < 64; k8 += 8) {
            uint32_t a0 = f2tf32(Qs[r0 * QP + k8 + tg]);
            uint32_t a1 = f2tf32(Qs[r1 * QP + k8 + tg]);
            uint32_t a2 = f2tf32(Qs[r0 * QP + k8 + tg + 4]);
            uint32_t a3 = f2tf32(Qs[r1 * QP + k8 + tg + 4]);
#pragma unroll
            for (int nt = 0; nt < 8; nt++) {
                int ncol = nt * 8 + g;
                uint32_t b0 = f2tf32(Kp[ncol * KP + k8 + tg]);
                uint32_t b1 = f2tf32(Kp[ncol * KP + k8 + tg + 4]);
                MMA_TF32(sf[nt], a0, a1, a2, a3, b0, b1);
            }
        }
#pragma unroll
        for (int nt = 0; nt < 8; nt++)
#pragma unroll
            for (int r = 0; r < 4; r++) sf[nt][r] *= 0.125f;   // 1/sqrt(HD)

        // ---- causal mask (diag tile only) ----
        if (kt == qt) {
            int gr0 = rowBase + r0, gr1 = rowBase + r1;
            int cb = kt * 64;
#pragma unroll
            for (int nt = 0; nt < 8; nt++) {
                int c0 = cb + nt * 8 + 2 * tg, c1 = c0 + 1;
                if (c0 > gr0) sf[nt][0] = -1e30f;
                if (c1 > gr0) sf[nt][1] = -1e30f;
                if (c0 > gr1) sf[nt][2] = -1e30f;
                if (c1 > gr1) sf[nt][3] = -1e30f;
            }
        }

        // ---- online softmax (registers only; quad-shuffle reductions) ----
        float mx0 = -INFINITY, mx1 = -INFINITY;
#pragma unroll
        for (int nt = 0; nt < 8; nt++) {
            mx0 = fmaxf(mx0, fmaxf(sf[nt][0], sf[nt][1]));
            mx1 = fmaxf(mx1, fmaxf(sf[nt][2], sf[nt][3]));
        }
        mx0 = fmaxf(mx0, __shfl_xor_sync(0xFFFFFFFF, mx0, 1));
        mx0 = fmaxf(mx0, __shfl_xor_sync(0xFFFFFFFF, mx0, 2));
        mx1 = fmaxf(mx1, __shfl_xor_sync(0xFFFFFFFF, mx1, 1));
        mx1 = fmaxf(mx1, __shfl_xor_sync(0xFFFFFFFF, mx1, 2));

        float mn0 = fmaxf(m0, mx0), mn1 = fmaxf(m1, mx1);
        float a0s = __expf(m0 - mn0), a1s = __expf(m1 - mn1);

        float rs0 = 0.f, rs1 = 0.f;
#pragma unroll
        for (int nt = 0; nt < 8; nt++) {
            sf[nt][0] = __expf(sf[nt][0] - mn0);
            sf[nt][1] = __expf(sf[nt][1] - mn0);
            sf[nt][2] = __expf(sf[nt][2] - mn1);
            sf[nt][3] = __expf(sf[nt][3] - mn1);
            rs0 += sf[nt][0] + sf[nt][1];
            rs1 += sf[nt][2] + sf[nt][3];
        }
        rs0 += __shfl_xor_sync(0xFFFFFFFF, rs0, 1);
        rs0 += __shfl_xor_sync(0xFFFFFFFF, rs0, 2);
        rs1 += __shfl_xor_sync(0xFFFFFFFF, rs1, 1);
        rs1 += __shfl_xor_sync(0xFFFFFFFF, rs1, 2);

        m0 = mn0; m1 = mn1;
        l0 = l0 * a0s + rs0;
        l1 = l1 * a1s + rs1;

        // ---- P to smem (only this warp's rows; warp-local reuse) ----
#pragma unroll
        for (int nt = 0; nt < 8; nt++) {
            int cc = nt * 8 + 2 * tg;
            *reinterpret_cast<float2*>(&Ps[r0 * PP + cc]) = make_float2(sf[nt][0], sf[nt][1]);
            *reinterpret_cast<float2*>(&Ps[r1 * PP + cc]) = make_float2(sf[nt][2], sf[nt][3]);
        }
        __syncwarp();

        // ---- O = O*alpha + P.V (TF32 MMA), V natural [n][d] ----
#pragma unroll
        for (int nt = 0; nt < 8; nt++) {
            of[nt][0] *= a0s; of[nt][1] *= a0s;
            of[nt][2] *= a1s; of[nt][3] *= a1s;
        }
        const float* Vp = Vs + s * 64 * VP;
#pragma unroll
        for (int k8 = 0; k8 < 64; k8 += 8) {
            uint32_t a0 = f2tf32(Ps[r0 * PP + k8 + tg]);
            uint32_t a1 = f2tf32(Ps[r1 * PP + k8 + tg]);
            uint32_t a2 = f2tf32(Ps[r0 * PP + k8 + tg + 4]);
            uint32_t a3 = f2tf32(Ps[r1 * PP + k8 + tg + 4]);
#pragma unroll
            for (int nt = 0; nt < 8; nt++) {
                int ncol = nt * 8 + g;
                uint32_t b0 = f2tf32(Vp[(k8 + tg) * VP + ncol]);
                uint32_t b1 = f2tf32(Vp[(k8 + tg + 4) * VP + ncol]);
                MMA_TF32(of[nt], a0, a1, a2, a3, b0, b1);
            }
        }
    }

    // ---- epilogue: y = O / l (fragment layout direct to gmem) ----
    float inv0 = 1.0f / l0, inv1 = 1.0f / l1;
    float* yr0 = yb + (size_t)(rowBase + r0) * C_;
    float* yr1 = yb + (size_t)(rowBase + r1) * C_;
#pragma unroll
    for (int nt = 0; nt < 8; nt++) {
        int cc = nt * 8 + 2 * tg;
        *reinterpret_cast<float2*>(yr0 + cc) = make_float2(of[nt][0] * inv0, of[nt][1] * inv0);
        *reinterpret_cast<float2*>(yr1 + cc) = make_float2(of[nt][2] * inv1, of[nt][3] * inv1);
    }
}

// ---------------- per-row NLL over V (single-pass online) ----------------
__global__ void nll_kernel(const float* __restrict__ logits,
                           const int* __restrict__ targets,
                           float* __restrict__ nll) {
    int row = blockIdx.x;
    const float* p = logits + (size_t)row * V_;
    int tid = threadIdx.x;
    float m = -INFINITY, s = 0.f;
    for (int c = tid; c < V_; c += 256) {
        float v = p[c];
        if (v <= m) {
            s += expf(v - m);
        } else {
            s = s * expf(m - v) + 1.0f;
            m = v;
        }
    }
    __shared__ float rm[256], rs[256];
    rm[tid] = m; rs[tid] = s; __syncthreads();
    for (int off = 128; off > 0; off >>= 1) {
        if (tid < off) {
            float m1 = rm[tid], s1 = rs[tid];
            float m2 = rm[tid + off], s2 = rs[tid + off];
            float M = fmaxf(m1, m2);
            rm[tid] = M;
            rs[tid] = s1 * expf(m1 - M) + s2 * expf(m2 - M);
        }
        __syncthreads();
    }
    if (tid == 0) {
        float lt = p[targets[row]];
        nll[row] = -(lt - rm[0] - logf(rs[0]));
    }
}

__global__ void loss_kernel(const float* __restrict__ nll, float* __restrict__ out) {
    __shared__ float red[256];
    int tid = threadIdx.x;
    float s = 0.f;
    for (int c = tid; c < MTOT; c += 256) s += nll[c];
    red[tid] = s; __syncthreads();
    for (int off = 128; off > 0; off >>= 1) {
        if (tid < off) red[tid] += red[tid + off];
        __syncthreads();
    }
    if (tid == 0) out[0] = red[0] * (1.0f / MTOT);
}

// ---------------- host launcher ----------------
extern "C" void kernel_launch(void* const* d_in, const int* in_sizes, int n_in,
                              void* d_out, int out_size) {
    const int*   idx     = (const int*)d_in[0];
    const int*   targets = (const int*)d_in[1];
    const float* tok     = (const float*)d_in[2];
    const float* pos     = (const float*)d_in[3];
    const float* ln1w    = (const float*)d_in[4];
    const float* ln1b    = (const float*)d_in[5];
    const float* ln2w    = (const float*)d_in[6];
    const float* ln2b    = (const float*)d_in[7];
    const float* Wq      = (const float*)d_in[8];
    const float* bq      = (const float*)d_in[9];
    const float* Wk      = (const float*)d_in[10];
    const float* bk      = (const float*)d_in[11];
    const float* Wv      = (const float*)d_in[12];
    const float* bv      = (const float*)d_in[13];
    const float* Wo      = (const float*)d_in[14];
    const float* bo      = (const float*)d_in[15];
    const float* W1      = (const float*)d_in[16];
    const float* b1      = (const float*)d_in[17];
    const float* W2      = (const float*)d_in[18];
    const float* b2      = (const float*)d_in[19];
    const float* lnfw    = (const float*)d_in[20];
    const float* lnfb    = (const float*)d_in[21];
    const float* headw   = (const float*)d_in[22];
    float* out = (float*)d_out;

    float *x, *h, *q, *k, *v, *y, *mlp, *nllbuf, *lgs;
    cudaGetSymbolAddress((void**)&x, g_x);
    cudaGetSymbolAddress((void**)&h, g_h);
    cudaGetSymbolAddress((void**)&q, g_q);
    cudaGetSymbolAddress((void**)&k, g_k);
    cudaGetSymbolAddress((void**)&v, g_v);
    cudaGetSymbolAddress((void**)&y, g_y);
    cudaGetSymbolAddress((void**)&mlp, g_mlp);
    cudaGetSymbolAddress((void**)&nllbuf, g_nll);
    cudaGetSymbolAddress((void**)&lgs, g_logits);

    cudaFuncSetAttribute(flash_attn_kernel,
                         cudaFuncAttributeMaxDynamicSharedMemorySize, FLASH_SMEM);
    cudaFuncSetAttribute(gemm_qkv_tf32_kernel,
                         cudaFuncAttributeMaxDynamicSharedMemorySize, GEMM_SMEM(64, 5));
    cudaFuncSetAttribute(gemm_tf32_kernel<0, false, false, true>,
                         cudaFuncAttributeMaxDynamicSharedMemorySize, GEMM_SMEM(128, 4));
    cudaFuncSetAttribute(gemm64_tf32_kernel<0, true, true>,
                         cudaFuncAttributeMaxDynamicSharedMemorySize, GEMM_SMEM(64, 5));
    cudaFuncSetAttribute(gemm64_tf32_kernel<1, true, false>,
                         cudaFuncAttributeMaxDynamicSharedMemorySize, GEMM_SMEM(64, 5));

    const size_t BTV = (size_t)MTOT * V_;
    float* logits = ((size_t)out_size >= BTV) ? out : lgs;

    embed_kernel<<<MTOT, 256>>>(idx, tok, pos, x);

    dim3 gQKV(C_ / 128, MTOT / 64, 3);                  // 768 CTAs
    dim3 gC64(C_ / 128, MTOT / 64);                     // 256 CTAs (Wo, FC2)
    dim3 gF64(FF_ / 128, MTOT / 64);                    // 1024 CTAs (FC1)
    dim3 gHsw(MTOT / 128, (V_ + 127) / 128);            // head GEMM, row-fastest (L2 B reuse)
    dim3 gFA(T_ / 64, B_ * H_);                         // flash attention: 512 CTAs

    for (int l = 0; l < L_; l++) {
        const size_t oC = (size_t)l * C_;
        const size_t oCC = (size_t)l * C_ * C_;
        const size_t oCF = (size_t)l * C_ * FF_;

        layernorm_kernel<<<MTOT, 256>>>(x, ln1w + oC, ln1b + oC, h);

        gemm_qkv_tf32_kernel<<<gQKV, 128, GEMM_SMEM(64, 5)>>>(h, Wq + oCC, Wk + oCC,
                                                              Wv + oCC, bq + oC, bk + oC,
                                                              bv + oC, q, k, v);

        flash_attn_kernel<<<gFA, 128, FLASH_SMEM>>>(q, k, v, y);

        gemm64_tf32_kernel<0, true, true><<<gC64, 128, GEMM_SMEM(64, 5)>>>(
            y, C_, Wo + oCC, C_, bo + oC, x, C_, x, C_, MTOT, C_, C_);

        layernorm_kernel<<<MTOT, 256>>>(x, ln2w + oC, ln2b + oC, h);

        gemm64_tf32_kernel<1, true, false><<<gF64, 128, GEMM_SMEM(64, 5)>>>(
            h, C_, W1 + oCF, FF_, b1 + (size_t)l * FF_, nullptr, 0, mlp, FF_, MTOT, FF_, C_);
        gemm64_tf32_kernel<0, true, true><<<gC64, 128, GEMM_SMEM(64, 5)>>>(
            mlp, FF_, W2 + oCF, C_, b2 + oC, x, C_, x, C_, MTOT, C_, FF_);
    }

    layernorm_kernel<<<MTOT, 256>>>(x, lnfw, lnfb, h);
    gemm_tf32_kernel<0, false, false, true><<<gHsw, 128, GEMM_SMEM(128, 4)>>>(
        h, C_, headw, V_, nullptr, nullptr, 0, logits, V_, MTOT, V_, C_);

    nll_kernel<<<MTOT, 256>>>(logits, targets, nllbuf);
    if ((size_t)out_size == BTV + 1) {
        loss_kernel<<<1, 256>>>(nllbuf, out + BTV);
    } else if ((size_t)out_size < BTV && out_size >= 1) {
        loss_kernel<<<1, 256>>>(nllbuf, out);
    }
}

// round 13
// speedup vs baseline: 1.6966x; 1.5658x over previous
#include <cuda_runtime.h>
#include <cuda_fp16.h>
#include <math.h>
#include <stdint.h>

// ---------------- problem constants ----------------
#define B_ 2
#define T_ 1024
#define C_ 1024
#define H_ 16
#define HD_ 64
#define L_ 12
#define V_ 50257
#define VP_ 50304            // V padded to multiple of 128
#define MTOT (B_ * T_)       // 2048 token rows
#define FF_ (4 * C_)         // 4096

// ---------------- static device scratch ----------------
__device__ float  g_x[MTOT * C_];                 // residual stream (fp32)
__device__ __half g_h[MTOT * C_];                 // LN outputs (GEMM A input)
__device__ float  g_q[MTOT * C_];
__device__ float  g_k[MTOT * C_];
__device__ float  g_v[MTOT * C_];
__device__ __half g_y[MTOT * C_];                 // attention out (Wo A input)
__device__ __half g_mlp[MTOT * FF_];              // FC1 out (FC2 A input)
__device__ float  g_nll[MTOT];
__device__ float  g_logits[(size_t)MTOT * V_];
// fp16 transposed weights [N][K]
__device__ __half g_wtq[(size_t)L_ * C_ * C_];
__device__ __half g_wtk[(size_t)L_ * C_ * C_];
__device__ __half g_wtv[(size_t)L_ * C_ * C_];
__device__ __half g_wto[(size_t)L_ * C_ * C_];
__device__ __half g_wt1[(size_t)L_ * FF_ * C_];   // [FF][C]
__device__ __half g_wt2[(size_t)L_ * C_ * FF_];   // [C][FF]
__device__ __half g_wth[(size_t)VP_ * C_];        // [VP][C] (pad rows stay zero)

// ---------------- helpers ----------------
__device__ __forceinline__ float gelu_exact(float v) {
    return 0.5f * v * (1.0f + erff(v * 0.7071067811865476f));
}
__device__ __forceinline__ uint32_t f2tf32(float x) {
    uint32_t r;
    asm("cvt.rna.tf32.f32 %0, %1;" : "=r"(r) : "f"(x));
    return r;
}
__device__ __forceinline__ uint32_t smem_u32(const void* p) {
    return (uint32_t)__cvta_generic_to_shared(p);
}

#define MMA_TF32(c, a0, a1, a2, a3, b0, b1)                                  \
    asm volatile(                                                            \
        "mma.sync.aligned.m16n8k8.row.col.f32.tf32.tf32.f32 "                \
        "{%0,%1,%2,%3}, {%4,%5,%6,%7}, {%8,%9}, {%0,%1,%2,%3};\n"            \
        : "+f"((c)[0]), "+f"((c)[1]), "+f"((c)[2]), "+f"((c)[3])             \
        : "r"(a0), "r"(a1), "r"(a2), "r"(a3), "r"(b0), "r"(b1))

#define MMA_F16(c, a0, a1, a2, a3, b0, b1)                                   \
    asm volatile(                                                            \
        "mma.sync.aligned.m16n8k16.row.col.f32.f16.f16.f32 "                 \
        "{%0,%1,%2,%3}, {%4,%5,%6,%7}, {%8,%9}, {%0,%1,%2,%3};\n"            \
        : "+f"((c)[0]), "+f"((c)[1]), "+f"((c)[2]), "+f"((c)[3])             \
        : "r"(a0), "r"(a1), "r"(a2), "r"(a3), "r"(b0), "r"(b1))

#define CP_ASYNC16(dst, src)                                                 \
    asm volatile("cp.async.cg.shared.global [%0], [%1], 16;"                 \
                 :: "r"(dst), "l"(src))
#define CP_COMMIT() asm volatile("cp.async.commit_group;")

// ---------------- weight prep: transpose + fp16 convert ----------------
// src [R][Cc] fp32 row-major -> dst [Cc][R] half (row stride dstStride)
__global__ void transpose_h_kernel(const float* __restrict__ src,
                                   __half* __restrict__ dst,
                                   int R, int Cc, int dstStride,
                                   size_t zsrc, size_t zdst) {
    __shared__ float tile[32][33];
    const float* s = src + (size_t)blockIdx.z * zsrc;
    __half* d = dst + (size_t)blockIdx.z * zdst;
    int cb = blockIdx.x * 32, rb = blockIdx.y * 32;
    int tx = threadIdx.x, ty = threadIdx.y;   // 32 x 8
#pragma unroll
    for (int j = 0; j < 4; j++) {
        int r = rb + ty + j * 8, c = cb + tx;
        if (r < R && c < Cc) tile[ty + j * 8][tx] = s[(size_t)r * Cc + c];
    }
    __syncthreads();
#pragma unroll
    for (int j = 0; j < 4; j++) {
        int c = cb + ty + j * 8, r = rb + tx;
        if (c < Cc && r < R)
            d[(size_t)c * dstStride + r] = __float2half_rn(tile[tx][ty + j * 8]);
    }
}

// ---------------- embedding ----------------
__global__ void embed_kernel(const int* __restrict__ idx,
                             const float* __restrict__ tok,
                             const float* __restrict__ pos,
                             float* __restrict__ x) {
    int row = blockIdx.x;
    int t = row % T_;
    int id = idx[row];
    const float* tr = tok + (size_t)id * C_;
    const float* pr = pos + (size_t)t * C_;
    float* xr = x + (size_t)row * C_;
#pragma unroll
    for (int j = 0; j < 4; j++) {
        int c = threadIdx.x + j * 256;
        xr[c] = tr[c] + pr[c];
    }
}

// ---------------- layernorm: fp32 in, fp16 out (GEMM A input) ----------------
__global__ void layernorm_kernel(const float* __restrict__ x,
                                 const float* __restrict__ w,
                                 const float* __restrict__ b,
                                 __half* __restrict__ out) {
    int row = blockIdx.x;
    int tid = threadIdx.x;
    const float* xr = x + (size_t)row * C_;
    float v[4];
    float s = 0.f;
#pragma unroll
    for (int j = 0; j < 4; j++) { v[j] = xr[tid + j * 256]; s += v[j]; }
    __shared__ float red[256];
    red[tid] = s; __syncthreads();
    for (int off = 128; off > 0; off >>= 1) {
        if (tid < off) red[tid] += red[tid + off];
        __syncthreads();
    }
    float mu = red[0] * (1.0f / C_);
    __syncthreads();
    float s2 = 0.f;
#pragma unroll
    for (int j = 0; j < 4; j++) { float d = v[j] - mu; s2 += d * d; }
    red[tid] = s2; __syncthreads();
    for (int off = 128; off > 0; off >>= 1) {
        if (tid < off) red[tid] += red[tid + off];
        __syncthreads();
    }
    float var = red[0] * (1.0f / C_);
    float rstd = rsqrtf(var + 1e-5f);
    __half* orow = out + (size_t)row * C_;
#pragma unroll
    for (int j = 0; j < 4; j++) {
        int c = tid + j * 256;
        orow[c] = __float2half_rn((v[j] - mu) * rstd * w[c] + b[c]);
    }
}

// ---------------- FP16 tensor-core GEMM (m16n8k16), cp.async 4-stage -------
// A [M][K] half row-major; BT [N][K] half row-major (pre-transposed weights).
// smem tiles in half2 (uint32) units: [rows][16 k-pairs], stride 20 words.
// Warp grid 2x2; warp tile (BM/2) x 64. BK = 32 halves per chunk.
#define AS20 20
#define G64_SMEM  ((64 * AS20 + 128 * AS20) * 4 * 4)    // 61440 B
#define G128_SMEM ((128 * AS20 + 128 * AS20) * 4 * 4)   // 81920 B

template <int BM, int STAGES, int ACT, bool HAS_BIAS, bool HAS_RES, bool OUT_HALF>
__device__ __forceinline__ void gemm16_body(const __half* __restrict__ A, int lda,
                                            const __half* __restrict__ BT, int ldb,
                                            const float* __restrict__ bias,
                                            const float* __restrict__ resid, int ldr,
                                            void* __restrict__ Cm, int ldc,
                                            int N, int K, int rowBase, int colBase) {
    constexpr int ASE = BM * AS20;
    constexpr int BSE = 128 * AS20;
    constexpr int MT = BM / 32;
    extern __shared__ uint32_t us[];
    uint32_t* As = us;
    uint32_t* Bs = us + STAGES * ASE;

    const int tid = threadIdx.x;
    const int lane = tid & 31, warp = tid >> 5;
    const int g = lane >> 2, tg = lane & 3;
    const int wm = warp >> 1, wn = warp & 1;

    float c[MT][8][4];
#pragma unroll
    for (int i = 0; i < MT; i++)
#pragma unroll
        for (int j = 0; j < 8; j++)
#pragma unroll
            for (int r = 0; r < 4; r++) c[i][j][r] = 0.f;

    auto loadA = [&](int s, int k0) {     // k0 in halves
        uint32_t* Ad = As + s * ASE;
#pragma unroll
        for (int i = 0; i < BM / 32; i++) {
            int lin = tid + i * 128;
            int r = lin >> 2, c4 = lin & 3;
            CP_ASYNC16(smem_u32(&Ad[r * AS20 + c4 * 4]),
                       A + (size_t)(rowBase + r) * lda + k0 + c4 * 8);
        }
    };
    auto loadB = [&](int s, int k0) {
        uint32_t* Bd = Bs + s * BSE;
#pragma unroll
        for (int i = 0; i < 4; i++) {
            int lin = tid + i * 128;
            int r = lin >> 2, c4 = lin & 3;
            CP_ASYNC16(smem_u32(&Bd[r * AS20 + c4 * 4]),
                       BT + (size_t)(colBase + r) * ldb + k0 + c4 * 8);
        }
    };

    const int nc = K >> 5;               // K / 32 halves
#pragma unroll
    for (int s = 0; s < STAGES - 1; s++) {
        loadA(s, s * 32);
        loadB(s, s * 32);
        CP_COMMIT();
    }

    int cs = 0, ls = STAGES - 1;
    for (int t = 0; t < nc; t++) {
        asm volatile("cp.async.wait_group %0;" :: "n"(STAGES - 2) : "memory");
        __syncthreads();
        int ld = t + STAGES - 1;
        if (ld < nc) {
            loadA(ls, ld * 32);
            loadB(ls, ld * 32);
        }
        CP_COMMIT();
        if (++ls == STAGES) ls = 0;

        const uint32_t* Ap = As + cs * ASE;
        const uint32_t* Bp = Bs + cs * BSE;
        if (++cs == STAGES) cs = 0;
#pragma unroll
        for (int ks = 0; ks < 2; ks++) {      // two m16n8k16 steps per 32-half chunk
            const int kp = ks * 8 + tg;
            uint32_t af[MT][4], bf[8][2];
#pragma unroll
            for (int mt = 0; mt < MT; mt++) {
                int mrow = wm * (BM / 2) + mt * 16 + g;
                af[mt][0] = Ap[mrow * AS20 + kp];
                af[mt][1] = Ap[(mrow + 8) * AS20 + kp];
                af[mt][2] = Ap[mrow * AS20 + kp + 4];
                af[mt][3] = Ap[(mrow + 8) * AS20 + kp + 4];
            }
#pragma unroll
            for (int nt = 0; nt < 8; nt++) {
                int ncol = wn * 64 + nt * 8 + g;
                bf[nt][0] = Bp[ncol * AS20 + kp];
                bf[nt][1] = Bp[ncol * AS20 + kp + 4];
            }
#pragma unroll
            for (int mt = 0; mt < MT; mt++)
#pragma unroll
                for (int nt = 0; nt < 8; nt++)
                    MMA_F16(c[mt][nt], af[mt][0], af[mt][1], af[mt][2], af[mt][3],
                            bf[nt][0], bf[nt][1]);
        }
    }

    // ---- epilogue ----
    const bool vecC = ((ldc & 1) == 0);
#pragma unroll
    for (int mt = 0; mt < MT; mt++) {
#pragma unroll
        for (int ri = 0; ri < 2; ri++) {
            int gr = rowBase + wm * (BM / 2) + mt * 16 + g + ri * 8;
#pragma unroll
            for (int nt = 0; nt < 8; nt++) {
                int gc = colBase + wn * 64 + nt * 8 + 2 * tg;
                if (gc >= N) continue;
                bool in1 = (gc + 1) < N;
                float v0 = c[mt][nt][ri * 2 + 0];
                float v1 = c[mt][nt][ri * 2 + 1];
                if (HAS_BIAS) { v0 += bias[gc]; if (in1) v1 += bias[gc + 1]; }
                if (ACT == 1) { v0 = gelu_exact(v0); if (in1) v1 = gelu_exact(v1); }
                if (HAS_RES) {
                    v0 += resid[(size_t)gr * ldr + gc];
                    if (in1) v1 += resid[(size_t)gr * ldr + gc + 1];
                }
                if (OUT_HALF) {
                    // OUT_HALF used only where N % 128 == 0 and gc even
                    __half2* cp = reinterpret_cast<__half2*>(
                        (__half*)Cm + (size_t)gr * ldc + gc);
                    *cp = __floats2half2_rn(v0, v1);
                } else {
                    float* cp = (float*)Cm + (size_t)gr * ldc + gc;
                    if (vecC && in1) {
                        *reinterpret_cast<float2*>(cp) = make_float2(v0, v1);
                    } else {
                        cp[0] = v0;
                        if (in1) cp[1] = v1;
                    }
                }
            }
        }
    }
}

// BM=64, 4-stage, 3 CTAs/SM — all layer GEMMs
template <int ACT, bool HAS_BIAS, bool HAS_RES, bool OUT_HALF>
__global__ void __launch_bounds__(128, 3)
gemm16_64_kernel(const __half* __restrict__ A, int lda,
                 const __half* __restrict__ BT, int ldb,
                 const float* __restrict__ bias,
                 const float* __restrict__ resid, int ldr,
                 void* __restrict__ Cm, int ldc, int N, int K) {
    gemm16_body<64, 4, ACT, HAS_BIAS, HAS_RES, OUT_HALF>(
        A, lda, BT, ldb, bias, resid, ldr, Cm, ldc, N, K,
        blockIdx.y * 64, blockIdx.x * 128);
}

// BM=128, 4-stage, SWAP grid (rows fastest) — head GEMM
template <int ACT, bool HAS_BIAS, bool HAS_RES, bool OUT_HALF>
__global__ void __launch_bounds__(128, 2)
gemm16_128sw_kernel(const __half* __restrict__ A, int lda,
                    const __half* __restrict__ BT, int ldb,
                    const float* __restrict__ bias,
                    const float* __restrict__ resid, int ldr,
                    void* __restrict__ Cm, int ldc, int N, int K) {
    gemm16_body<128, 4, ACT, HAS_BIAS, HAS_RES, OUT_HALF>(
        A, lda, BT, ldb, bias, resid, ldr, Cm, ldc, N, K,
        blockIdx.x * 128, blockIdx.y * 128);
}

// fused QKV (BM=64): blockIdx.z selects projection; fp32 outputs
__global__ void __launch_bounds__(128, 3)
qkv16_kernel(const __half* __restrict__ h,
             const __half* __restrict__ wtq, const __half* __restrict__ wtk,
             const __half* __restrict__ wtv,
             const float* __restrict__ bq, const float* __restrict__ bk,
             const float* __restrict__ bv,
             float* __restrict__ qo, float* __restrict__ ko,
             float* __restrict__ vo) {
    const __half* BT; const float* bias; float* Cm;
    if (blockIdx.z == 0)      { BT = wtq; bias = bq; Cm = qo; }
    else if (blockIdx.z == 1) { BT = wtk; bias = bk; Cm = ko; }
    else                      { BT = wtv; bias = bv; Cm = vo; }
    gemm16_body<64, 4, 0, true, false, false>(h, C_, BT, C_, bias, nullptr, 0,
                                              Cm, C_, C_, C_,
                                              blockIdx.y * 64, blockIdx.x * 128);
}

// ---------------- fused flash attention (tf32 mma; y output -> fp16) -------
#define QP 68
#define KP 68
#define VPD 72
#define PP 68
#define FLASH_SMEM ((64 * QP + 2 * 64 * KP + 2 * 64 * VPD + 64 * PP) * 4)

__global__ void __launch_bounds__(128, 2)
flash_attn_kernel(const float* __restrict__ q, const float* __restrict__ k,
                  const float* __restrict__ v, __half* __restrict__ y) {
    extern __shared__ float sm[];
    float* Qs = sm;
    float* Ks = Qs + 64 * QP;
    float* Vs = Ks + 2 * 64 * KP;
    float* Ps = Vs + 2 * 64 * VPD;

    const int tid = threadIdx.x;
    const int lane = tid & 31, warp = tid >> 5;
    const int g = lane >> 2, tg = lane & 3;
    const int z = blockIdx.y;
    const int b = z >> 4, h = z & 15;
    const int qt = (T_ / 64 - 1) - blockIdx.x;
    const int rowBase = qt * 64;

    const float* qb = q + (size_t)b * T_ * C_ + h * HD_;
    const float* kb = k + (size_t)b * T_ * C_ + h * HD_;
    const float* vb = v + (size_t)b * T_ * C_ + h * HD_;
    __half* yb = y + (size_t)b * T_ * C_ + h * HD_;

    auto loadKV = [&](int s, int kt) {
        const float* kbt = kb + (size_t)kt * 64 * C_;
        const float* vbt = vb + (size_t)kt * 64 * C_;
        float* Kd = Ks + s * 64 * KP;
        float* Vd = Vs + s * 64 * VPD;
#pragma unroll
        for (int i = 0; i < 8; i++) {
            int lin = tid + i * 128;
            int n = lin >> 4, d4 = lin & 15;
            CP_ASYNC16(smem_u32(&Kd[n * KP + d4 * 4]), kbt + (size_t)n * C_ + d4 * 4);
        }
#pragma unroll
        for (int i = 0; i < 8; i++) {
            int lin = tid + i * 128;
            int n = lin >> 4, d4 = lin & 15;
            CP_ASYNC16(smem_u32(&Vd[n * VPD + d4 * 4]), vbt + (size_t)n * C_ + d4 * 4);
        }
    };

#pragma unroll
    for (int i = 0; i < 8; i++) {
        int lin = tid + i * 128;
        int mm = lin >> 4, d4 = lin & 15;
        CP_ASYNC16(smem_u32(&Qs[mm * QP + d4 * 4]), qb + (size_t)(rowBase + mm) * C_ + d4 * 4);
    }
    loadKV(0, 0);
    CP_COMMIT();

    const int r0 = warp * 16 + g, r1 = r0 + 8;
    float m0 = -INFINITY, m1 = -INFINITY, l0 = 0.f, l1 = 0.f;
    float of[8][4];
#pragma unroll
    for (int nt = 0; nt < 8; nt++)
#pragma unroll
        for (int r = 0; r < 4; r++) of[nt][r] = 0.f;

    for (int kt = 0; kt <= qt; kt++) {
        const int s = kt & 1;
        asm volatile("cp.async.wait_group 0;" ::: "memory");
        __syncthreads();
        if (kt < qt) loadKV(s ^ 1, kt + 1);
        CP_COMMIT();

        const float* Kp = Ks + s * 64 * KP;
        float sf[8][4];
#pragma unroll
        for (int nt = 0; nt < 8; nt++)
#pragma unroll
            for (int r = 0; r < 4; r++) sf[nt][r] = 0.f;
#pragma unroll
        for (int k8 = 0; k8 < 64; k8 += 8) {
            uint32_t a0 = f2tf32(Qs[r0 * QP + k8 + tg]);
            uint32_t a1 = f2tf32(Qs[r1 * QP + k8 + tg]);
            uint32_t a2 = f2tf32(Qs[r0 * QP + k8 + tg + 4]);
            uint32_t a3 = f2tf32(Qs[r1 * QP + k8 + tg + 4]);
#pragma unroll
            for (int nt = 0; nt < 8; nt++) {
                int ncol = nt * 8 + g;
                uint32_t b0 = f2tf32(Kp[ncol * KP + k8 + tg]);
                uint32_t b1 = f2tf32(Kp[ncol * KP + k8 + tg + 4]);
                MMA_TF32(sf[nt], a0, a1, a2, a3, b0, b1);
            }
        }
#pragma unroll
        for (int nt = 0; nt < 8; nt++)
#pragma unroll
            for (int r = 0; r < 4; r++) sf[nt][r] *= 0.125f;

        if (kt == qt) {
            int gr0 = rowBase + r0, gr1 = rowBase + r1;
            int cb = kt * 64;
#pragma unroll
            for (int nt = 0; nt < 8; nt++) {
                int c0 = cb + nt * 8 + 2 * tg, c1 = c0 + 1;
                if (c0 > gr0) sf[nt][0] = -1e30f;
                if (c1 > gr0) sf[nt][1] = -1e30f;
                if (c0 > gr1) sf[nt][2] = -1e30f;
                if (c1 > gr1) sf[nt][3] = -1e30f;
            }
        }

        float mx0 = -INFINITY, mx1 = -INFINITY;
#pragma unroll
        for (int nt = 0; nt < 8; nt++) {
            mx0 = fmaxf(mx0, fmaxf(sf[nt][0], sf[nt][1]));
            mx1 = fmaxf(mx1, fmaxf(sf[nt][2], sf[nt][3]));
        }
        mx0 = fmaxf(mx0, __shfl_xor_sync(0xFFFFFFFF, mx0, 1));
        mx0 = fmaxf(mx0, __shfl_xor_sync(0xFFFFFFFF, mx0, 2));
        mx1 = fmaxf(mx1, __shfl_xor_sync(0xFFFFFFFF, mx1, 1));
        mx1 = fmaxf(mx1, __shfl_xor_sync(0xFFFFFFFF, mx1, 2));

        float mn0 = fmaxf(m0, mx0), mn1 = fmaxf(m1, mx1);
        float a0s = __expf(m0 - mn0), a1s = __expf(m1 - mn1);

        float rs0 = 0.f, rs1 = 0.f;
#pragma unroll
        for (int nt = 0; nt < 8; nt++) {
            sf[nt][0] = __expf(sf[nt][0] - mn0);
            sf[nt][1] = __expf(sf[nt][1] - mn0);
            sf[nt][2] = __expf(sf[nt][2] - mn1);
            sf[nt][3] = __expf(sf[nt][3] - mn1);
            rs0 += sf[nt][0] + sf[nt][1];
            rs1 += sf[nt][2] + sf[nt][3];
        }
        rs0 += __shfl_xor_sync(0xFFFFFFFF, rs0, 1);
        rs0 += __shfl_xor_sync(0xFFFFFFFF, rs0, 2);
        rs1 += __shfl_xor_sync(0xFFFFFFFF, rs1, 1);
        rs1 += __shfl_xor_sync(0xFFFFFFFF, rs1, 2);

        m0 = mn0; m1 = mn1;
        l0 = l0 * a0s + rs0;
        l1 = l1 * a1s + rs1;

#pragma unroll
        for (int nt = 0; nt < 8; nt++) {
            int cc = nt * 8 + 2 * tg;
            *reinterpret_cast<float2*>(&Ps[r0 * PP + cc]) = make_float2(sf[nt][0], sf[nt][1]);
            *reinterpret_cast<float2*>(&Ps[r1 * PP + cc]) = make_float2(sf[nt][2], sf[nt][3]);
        }
        __syncwarp();

#pragma unroll
        for (int nt = 0; nt < 8; nt++) {
            of[nt][0] *= a0s; of[nt][1] *= a0s;
            of[nt][2] *= a1s; of[nt][3] *= a1s;
        }
        const float* Vp = Vs + s * 64 * VPD;
#pragma unroll
        for (int k8 = 0; k8 < 64; k8 += 8) {
            uint32_t a0 = f2tf32(Ps[r0 * PP + k8 + tg]);
            uint32_t a1 = f2tf32(Ps[r1 * PP + k8 + tg]);
            uint32_t a2 = f2tf32(Ps[r0 * PP + k8 + tg + 4]);
            uint32_t a3 = f2tf32(Ps[r1 * PP + k8 + tg + 4]);
#pragma unroll
            for (int nt = 0; nt < 8; nt++) {
                int ncol = nt * 8 + g;
                uint32_t b0 = f2tf32(Vp[(k8 + tg) * VPD + ncol]);
                uint32_t b1 = f2tf32(Vp[(k8 + tg + 4) * VPD + ncol]);
                MMA_TF32(of[nt], a0, a1, a2, a3, b0, b1);
            }
        }
    }

    // y = fp16(O / l)   (y is the Wo GEMM's A input)
    float inv0 = 1.0f / l0, inv1 = 1.0f / l1;
    __half* yr0 = yb + (size_t)(rowBase + r0) * C_;
    __half* yr1 = yb + (size_t)(rowBase + r1) * C_;
#pragma unroll
    for (int nt = 0; nt < 8; nt++) {
        int cc = nt * 8 + 2 * tg;
        *reinterpret_cast<__half2*>(yr0 + cc) =
            __floats2half2_rn(of[nt][0] * inv0, of[nt][1] * inv0);
        *reinterpret_cast<__half2*>(yr1 + cc) =
            __floats2half2_rn(of[nt][2] * inv1, of[nt][3] * inv1);
    }
}

// ---------------- per-row NLL over V (single-pass online) ----------------
__global__ void nll_kernel(const float* __restrict__ logits,
                           const int* __restrict__ targets,
                           float* __restrict__ nll) {
    int row = blockIdx.x;
    const float* p = logits + (size_t)row * V_;
    int tid = threadIdx.x;
    float m = -INFINITY, s = 0.f;
    for (int c = tid; c < V_; c += 256) {
        float v = p[c];
        if (v <= m) {
            s += expf(v - m);
        } else {
            s = s * expf(m - v) + 1.0f;
            m = v;
        }
    }
    __shared__ float rm[256], rs[256];
    rm[tid] = m; rs[tid] = s; __syncthreads();
    for (int off = 128; off > 0; off >>= 1) {
        if (tid < off) {
            float m1 = rm[tid], s1 = rs[tid];
            float m2 = rm[tid + off], s2 = rs[tid + off];
            float M = fmaxf(m1, m2);
            rm[tid] = M;
            rs[tid] = s1 * expf(m1 - M) + s2 * expf(m2 - M);
        }
        __syncthreads();
    }
    if (tid == 0) {
        float lt = p[targets[row]];
        nll[row] = -(lt - rm[0] - logf(rs[0]));
    }
}

__global__ void loss_kernel(const float* __restrict__ nll, float* __restrict__ out) {
    __shared__ float red[256];
    int tid = threadIdx.x;
    float s = 0.f;
    for (int c = tid; c < MTOT; c += 256) s += nll[c];
    red[tid] = s; __syncthreads();
    for (int off = 128; off > 0; off >>= 1) {
        if (tid < off) red[tid] += red[tid + off];
        __syncthreads();
    }
    if (tid == 0) out[0] = red[0] * (1.0f / MTOT);
}

// ---------------- host launcher ----------------
extern "C" void kernel_launch(void* const* d_in, const int* in_sizes, int n_in,
                              void* d_out, int out_size) {
    const int*   idx     = (const int*)d_in[0];
    const int*   targets = (const int*)d_in[1];
    const float* tok     = (const float*)d_in[2];
    const float* pos     = (const float*)d_in[3];
    const float* ln1w    = (const float*)d_in[4];
    const float* ln1b    = (const float*)d_in[5];
    const float* ln2w    = (const float*)d_in[6];
    const float* ln2b    = (const float*)d_in[7];
    const float* Wq      = (const float*)d_in[8];
    const float* bq      = (const float*)d_in[9];
    const float* Wk      = (const float*)d_in[10];
    const float* bk      = (const float*)d_in[11];
    const float* Wv      = (const float*)d_in[12];
    const float* bv      = (const float*)d_in[13];
    const float* Wo      = (const float*)d_in[14];
    const float* bo      = (const float*)d_in[15];
    const float* W1      = (const float*)d_in[16];
    const float* b1      = (const float*)d_in[17];
    const float* W2      = (const float*)d_in[18];
    const float* b2      = (const float*)d_in[19];
    const float* lnfw    = (const float*)d_in[20];
    const float* lnfb    = (const float*)d_in[21];
    const float* headw   = (const float*)d_in[22];
    float* out = (float*)d_out;

    float *x, *q, *k, *v, *nllbuf, *lgs;
    __half *h, *y, *mlp, *wtq, *wtk, *wtv, *wto, *wt1, *wt2, *wth;
    cudaGetSymbolAddress((void**)&x, g_x);
    cudaGetSymbolAddress((void**)&h, g_h);
    cudaGetSymbolAddress((void**)&q, g_q);
    cudaGetSymbolAddress((void**)&k, g_k);
    cudaGetSymbolAddress((void**)&v, g_v);
    cudaGetSymbolAddress((void**)&y, g_y);
    cudaGetSymbolAddress((void**)&mlp, g_mlp);
    cudaGetSymbolAddress((void**)&nllbuf, g_nll);
    cudaGetSymbolAddress((void**)&lgs, g_logits);
    cudaGetSymbolAddress((void**)&wtq, g_wtq);
    cudaGetSymbolAddress((void**)&wtk, g_wtk);
    cudaGetSymbolAddress((void**)&wtv, g_wtv);
    cudaGetSymbolAddress((void**)&wto, g_wto);
    cudaGetSymbolAddress((void**)&wt1, g_wt1);
    cudaGetSymbolAddress((void**)&wt2, g_wt2);
    cudaGetSymbolAddress((void**)&wth, g_wth);

    cudaFuncSetAttribute(flash_attn_kernel,
                         cudaFuncAttributeMaxDynamicSharedMemorySize, FLASH_SMEM);
    cudaFuncSetAttribute(qkv16_kernel,
                         cudaFuncAttributeMaxDynamicSharedMemorySize, G64_SMEM);
    cudaFuncSetAttribute(gemm16_64_kernel<0, true, true, false>,
                         cudaFuncAttributeMaxDynamicSharedMemorySize, G64_SMEM);
    cudaFuncSetAttribute(gemm16_64_kernel<1, true, false, true>,
                         cudaFuncAttributeMaxDynamicSharedMemorySize, G64_SMEM);
    cudaFuncSetAttribute(gemm16_128sw_kernel<0, false, false, false>,
                         cudaFuncAttributeMaxDynamicSharedMemorySize, G128_SMEM);

    const size_t BTV = (size_t)MTOT * V_;
    float* logits = ((size_t)out_size >= BTV) ? out : lgs;

    // ---- weight prep: transpose + fp16 convert (per launch, graph-capturable) ----
    dim3 tb(32, 8);
    const size_t CC = (size_t)C_ * C_, CF = (size_t)C_ * FF_;
    transpose_h_kernel<<<dim3(32, 32, 12), tb>>>(Wq, wtq, C_, C_, C_, CC, CC);
    transpose_h_kernel<<<dim3(32, 32, 12), tb>>>(Wk, wtk, C_, C_, C_, CC, CC);
    transpose_h_kernel<<<dim3(32, 32, 12), tb>>>(Wv, wtv, C_, C_, C_, CC, CC);
    transpose_h_kernel<<<dim3(32, 32, 12), tb>>>(Wo, wto, C_, C_, C_, CC, CC);
    transpose_h_kernel<<<dim3(FF_ / 32, 32, 12), tb>>>(W1, wt1, C_, FF_, C_, CF, CF);
    transpose_h_kernel<<<dim3(32, FF_ / 32, 12), tb>>>(W2, wt2, FF_, C_, FF_, CF, CF);
    transpose_h_kernel<<<dim3((V_ + 31) / 32, 32, 1), tb>>>(headw, wth, C_, V_, C_, 0, 0);

    embed_kernel<<<MTOT, 256>>>(idx, tok, pos, x);

    dim3 gQKV(C_ / 128, MTOT / 64, 3);           // 768 CTAs
    dim3 gC(C_ / 128, MTOT / 64);                // 256 CTAs (Wo, FC2)
    dim3 gF(FF_ / 128, MTOT / 64);               // 1024 CTAs (FC1)
    dim3 gH(MTOT / 128, VP_ / 128);              // head: rows fastest (L2 B reuse)
    dim3 gFA(T_ / 64, B_ * H_);

    for (int l = 0; l < L_; l++) {
        const size_t oC = (size_t)l * C_;
        const size_t oCC = (size_t)l * CC;
        const size_t oCF = (size_t)l * CF;

        layernorm_kernel<<<MTOT, 256>>>(x, ln1w + oC, ln1b + oC, h);

        qkv16_kernel<<<gQKV, 128, G64_SMEM>>>(h, wtq + oCC, wtk + oCC, wtv + oCC,
                                              bq + oC, bk + oC, bv + oC, q, k, v);

        flash_attn_kernel<<<gFA, 128, FLASH_SMEM>>>(q, k, v, y);

        gemm16_64_kernel<0, true, true, false><<<gC, 128, G64_SMEM>>>(
            y, C_, wto + oCC, C_, bo + oC, x, C_, x, C_, C_, C_);

        layernorm_kernel<<<MTOT, 256>>>(x, ln2w + oC, ln2b + oC, h);

        gemm16_64_kernel<1, true, false, true><<<gF, 128, G64_SMEM>>>(
            h, C_, wt1 + oCF, C_, b1 + (size_t)l * FF_, nullptr, 0, mlp, FF_, FF_, C_);
        gemm16_64_kernel<0, true, true, false><<<gC, 128, G64_SMEM>>>(
            mlp, FF_, wt2 + oCF, FF_, b2 + oC, x, C_, x, C_, C_, FF_);
    }

    layernorm_kernel<<<MTOT, 256>>>(x, lnfw, lnfb, h);
    gemm16_128sw_kernel<0, false, false, false><<<gH, 128, G128_SMEM>>>(
        h, C_, wth, C_, nullptr, nullptr, 0, logits, V_, V_, C_);

    nll_kernel<<<MTOT, 256>>>(logits, targets, nllbuf);
    if ((size_t)out_size == BTV + 1) {
        loss_kernel<<<1, 256>>>(nllbuf, out + BTV);
    } else if ((size_t)out_size < BTV && out_size >= 1) {
        loss_kernel<<<1, 256>>>(nllbuf, out);
    }
}